// round 7
// baseline (speedup 1.0000x reference)
#include <cuda_runtime.h>
#include <cuda_bf16.h>
#include <math.h>
#include <stdint.h>

#define B_SZ   512
#define T_SZ   128
#define HID    1024
#define EMB    512
#define GATES  4096
#define WK     1024      // recurrent K (h only)
#define NCH    8         // chunks of 128 K-bytes (int8) = WK/128

// ---------------- device scratch (allocation-free) ----------------
__device__ __align__(128) int8_t g_We0[GATES * WK];   // [p][k] permuted N-major, digit0
__device__ __align__(128) int8_t g_We1[GATES * WK];   // digit1
__device__ float g_sc[GATES];                          // per permuted column scale s
__device__ float g_s1[GATES];                          // s/127
__device__ float g_s2[GATES];                          // s/16129
__device__ float g_Ep[1024 * GATES];                   // E'[vocab][p]: emb@Wx + b (+1 on f)
__device__ __align__(128) int8_t g_hd0[2][B_SZ * HID]; // h digit0, double-buffered
__device__ __align__(128) int8_t g_hd1[2][B_SZ * HID]; // h digit1
__device__ float g_hf[B_SZ * HID];                     // fp32 h (final projection)
__device__ float g_c[B_SZ * HID];
__device__ unsigned g_bar;                             // device-wide step barrier

// ---------------- helpers ----------------
__device__ __forceinline__ uint32_t smem_u32(const void* p) {
    uint32_t r;
    asm("{ .reg .u64 t; cvta.to.shared.u64 t, %1; cvt.u32.u64 %0, t; }" : "=r"(r) : "l"(p));
    return r;
}
__device__ __forceinline__ void cpa16(uint32_t dst, const void* src) {
    asm volatile("cp.async.cg.shared.global [%0], [%1], 16;" :: "r"(dst), "l"(src) : "memory");
}
#define CP_COMMIT() asm volatile("cp.async.commit_group;" ::: "memory")
#define CP_WAIT2()  asm volatile("cp.async.wait_group 2;" ::: "memory")
#define CP_WAIT1()  asm volatile("cp.async.wait_group 1;" ::: "memory")
#define CP_WAIT0()  asm volatile("cp.async.wait_group 0;" ::: "memory")

#define LDMX4(r, addr) \
    asm volatile("ldmatrix.sync.aligned.m8n8.x4.shared.b16 {%0,%1,%2,%3}, [%4];" \
        : "=r"((r)[0]), "=r"((r)[1]), "=r"((r)[2]), "=r"((r)[3]) : "r"(addr))

// int8 MMA: m16n8k32, s32 accum
#define IMMA(acc, a, b0, b1) \
    asm volatile("mma.sync.aligned.m16n8k32.row.col.s32.s8.s8.s32 " \
        "{%0,%1,%2,%3}, {%4,%5,%6,%7}, {%8,%9}, {%0,%1,%2,%3};" \
        : "+r"((acc)[0]), "+r"((acc)[1]), "+r"((acc)[2]), "+r"((acc)[3]) \
        : "r"((a)[0]), "r"((a)[1]), "r"((a)[2]), "r"((a)[3]), "r"(b0), "r"(b1))

#define SW(o) ((uint32_t)(o) ^ ((((uint32_t)(o)) >> 3) & 0x70))

__device__ __forceinline__ float sigm(float x) { return 1.0f / (1.0f + __expf(-x)); }
__device__ __forceinline__ float tanh_f(float x) {
    float e = __expf(2.0f * x);
    return 1.0f - 2.0f / (e + 1.0f);
}

// smem: 3 stages; each stage = 4 regions (A0/A1/B0/B1) of 128 rows x 128B
#define OFF_A0    0
#define OFF_A1    16384
#define OFF_B0    32768
#define OFF_B1    49152
#define STAGE_SZ  65536
#define STEP_SMEM (3 * STAGE_SZ)   // 196608

// ================= persistent LSTM: all 128 steps, int8 3-pass IMMA =================
__global__ void __launch_bounds__(256, 1)
lstm_persist(const int* __restrict__ message)
{
    extern __shared__ __align__(1024) char smem[];
    const uint32_t sm = smem_u32(smem);
    const int tid  = threadIdx.x;
    const int lane = tid & 31;
    const int wid  = tid >> 5;
    const int bx   = blockIdx.x;           // n-tile 0..31 (permuted cols)
    const int bm   = blockIdx.y * 128;     // m-tile base row

    // ---- fixed per-thread load addressing: chunk = 128 K-bytes per row ----
    const int r    = tid >> 1;             // 0..127 tile row
    const int half = tid & 1;              // which 64B half of the 128B chunk row
    const char* bW0 = (const char*)(g_We0 + (size_t)(bx * 128 + r) * WK);
    const char* bW1 = (const char*)(g_We1 + (size_t)(bx * 128 + r) * WK);
    const char* hD0[2] = { (const char*)(g_hd0[0] + (size_t)(bm + r) * HID),
                           (const char*)(g_hd0[1] + (size_t)(bm + r) * HID) };
    const char* hD1[2] = { (const char*)(g_hd1[0] + (size_t)(bm + r) * HID),
                           (const char*)(g_hd1[1] + (size_t)(bm + r) * HID) };
    const uint32_t swoff[4] = {
        SW(r * 128 + half * 64 + 0),  SW(r * 128 + half * 64 + 16),
        SW(r * 128 + half * 64 + 32), SW(r * 128 + half * 64 + 48) };
    const int gb0 = half * 64;

    // ---- warp compute layout: 2(M) x 4(N) warps; warp tile 64x32 ----
    const int wm = (wid >> 2) * 64;
    const int wn = (wid & 3) * 32;
    const int aRow = (lane & 15);
    const int aSel = ((lane >> 4) & 1) * 16;
    const int bRowBase = (lane & 7) + ((lane >> 4) & 1) * 8;
    const int bSel = ((lane >> 3) & 1) * 16;

    // per-thread output column scales (fixed across steps)
    float s1v[4][2], s2v[4][2];
    #pragma unroll
    for (int n8 = 0; n8 < 4; n8++) {
        const int p = bx * 128 + wn + n8 * 8 + (lane & 3) * 2;
        s1v[n8][0] = g_s1[p];     s1v[n8][1] = g_s1[p + 1];
        s2v[n8][0] = g_s2[p];     s2v[n8][1] = g_s2[p + 1];
    }

    // epilogue addressing (threads 0..127)
    const int erow = bm + tid;
    const int* msgp = message + erow * T_SZ;
    float* crow = g_c + (size_t)erow * HID + bx * 32;
    float* hrow = g_hf + (size_t)erow * HID + bx * 32;
    float* smC = (float*)smem;

    #pragma unroll 1
    for (int t = 0; t < T_SZ; t++) {
        const char* aH0 = hD0[t & 1];
        const char* aH1 = hD1[t & 1];

        int acc1[4][4][4], acc2[4][4][4];
        #pragma unroll
        for (int i = 0; i < 4; i++)
            #pragma unroll
            for (int j = 0; j < 4; j++)
                #pragma unroll
                for (int k = 0; k < 4; k++) { acc1[i][j][k] = 0; acc2[i][j][k] = 0; }

        // ---- prefetch chunks 0,1 into slots 0,1 ----
        #pragma unroll
        for (int c = 0; c < 2; c++) {
            const uint32_t dst = sm + c * STAGE_SZ;
            const int kb = c * 128;
            #pragma unroll
            for (int u = 0; u < 4; u++) {
                const int gb = kb + gb0 + u * 16;
                cpa16(dst + OFF_A0 + swoff[u], aH0 + gb);
                cpa16(dst + OFF_A1 + swoff[u], aH1 + gb);
                cpa16(dst + OFF_B0 + swoff[u], bW0 + gb);
                cpa16(dst + OFF_B1 + swoff[u], bW1 + gb);
            }
            CP_COMMIT();
        }

        int sc = 0, sp = 2;
        #pragma unroll 1
        for (int c = 0; c < NCH; c++) {
            if (c < NCH - 2)      { CP_WAIT2(); }
            else if (c == NCH - 2){ CP_WAIT1(); }
            else                  { CP_WAIT0(); }
            __syncthreads();   // chunk c visible; every warp done with slot sp

            if (c + 2 < NCH) {
                const uint32_t dst = sm + sp * STAGE_SZ;
                const int kb = (c + 2) * 128;
                #pragma unroll
                for (int u = 0; u < 4; u++) {
                    const int gb = kb + gb0 + u * 16;
                    cpa16(dst + OFF_A0 + swoff[u], aH0 + gb);
                    cpa16(dst + OFF_A1 + swoff[u], aH1 + gb);
                    cpa16(dst + OFF_B0 + swoff[u], bW0 + gb);
                    cpa16(dst + OFF_B1 + swoff[u], bW1 + gb);
                }
                CP_COMMIT();
            }

            const uint32_t stage = sm + sc * STAGE_SZ;
            #pragma unroll
            for (int k32 = 0; k32 < 4; k32++) {
                const int kb = k32 * 32;
                uint32_t a0[4][4], a1[4][4], b0[2][4], b1[2][4];
                #pragma unroll
                for (int mi = 0; mi < 4; mi++) {
                    const uint32_t ao = SW((wm + mi * 16 + aRow) * 128 + kb + aSel);
                    LDMX4(a0[mi], stage + OFF_A0 + ao);
                    LDMX4(a1[mi], stage + OFF_A1 + ao);
                }
                #pragma unroll
                for (int nj = 0; nj < 2; nj++) {
                    const uint32_t bo = SW((wn + nj * 16 + bRowBase) * 128 + kb + bSel);
                    LDMX4(b0[nj], stage + OFF_B0 + bo);
                    LDMX4(b1[nj], stage + OFF_B1 + bo);
                }
                #pragma unroll
                for (int mi = 0; mi < 4; mi++) {
                    #pragma unroll
                    for (int n8 = 0; n8 < 4; n8++) {
                        const uint32_t e0b0 = b0[n8 >> 1][(n8 & 1) * 2];
                        const uint32_t e0b1 = b0[n8 >> 1][(n8 & 1) * 2 + 1];
                        const uint32_t e1b0 = b1[n8 >> 1][(n8 & 1) * 2];
                        const uint32_t e1b1 = b1[n8 >> 1][(n8 & 1) * 2 + 1];
                        IMMA(acc1[mi][n8], a0[mi], e0b0, e0b1);   // d0*e0
                        IMMA(acc2[mi][n8], a0[mi], e1b0, e1b1);   // d0*e1
                        IMMA(acc2[mi][n8], a1[mi], e0b0, e0b1);   // d1*e0
                    }
                }
            }
            sc = (sc == 2) ? 0 : sc + 1;
            sp = (sp == 2) ? 0 : sp + 1;
        }

        // ---- dequantize accs to fp32, stage to smem (stride 132) ----
        __syncthreads();
        #pragma unroll
        for (int mi = 0; mi < 4; mi++) {
            #pragma unroll
            for (int n8 = 0; n8 < 4; n8++) {
                const int row = wm + mi * 16 + (lane >> 2);
                const int col = wn + n8 * 8 + (lane & 3) * 2;
                const float f0 = (float)acc1[mi][n8][0] * s1v[n8][0] + (float)acc2[mi][n8][0] * s2v[n8][0];
                const float f1 = (float)acc1[mi][n8][1] * s1v[n8][1] + (float)acc2[mi][n8][1] * s2v[n8][1];
                const float f2 = (float)acc1[mi][n8][2] * s1v[n8][0] + (float)acc2[mi][n8][2] * s2v[n8][0];
                const float f3 = (float)acc1[mi][n8][3] * s1v[n8][1] + (float)acc2[mi][n8][3] * s2v[n8][1];
                smC[row * 132 + col]           = f0;
                smC[row * 132 + col + 1]       = f1;
                smC[(row + 8) * 132 + col]     = f2;
                smC[(row + 8) * 132 + col + 1] = f3;
            }
        }
        __syncthreads();

        // ---- fused epilogue: + E'[msg] then LSTM pointwise; requantize h ----
        if (tid < 128) {
            const int msg = msgp[t];
            const float* cr = smC + tid * 132;
            const float* ep = g_Ep + (size_t)msg * GATES + bx * 128;
            int8_t* h0p = g_hd0[(t + 1) & 1] + (size_t)erow * HID + bx * 32;
            int8_t* h1p = g_hd1[(t + 1) & 1] + (size_t)erow * HID + bx * 32;
            int8_t d0buf[32], d1buf[32];
            #pragma unroll 8
            for (int l = 0; l < 32; l++) {
                const float iv = cr[l]      + ep[l];
                const float gv = cr[32 + l] + ep[32 + l];
                const float fv = cr[64 + l] + ep[64 + l];
                const float ov = cr[96 + l] + ep[96 + l];
                const float cc = sigm(fv) * crow[l] + sigm(iv) * tanh_f(gv);
                const float hv = sigm(ov) * tanh_f(cc);
                crow[l] = cc;
                hrow[l] = hv;
                const float x = hv * 127.0f;
                const int d0 = __float2int_rn(x);
                const int d1 = __float2int_rn((x - (float)d0) * 127.0f);
                d0buf[l] = (int8_t)d0;
                d1buf[l] = (int8_t)d1;
            }
            #pragma unroll
            for (int u = 0; u < 2; u++) {
                *(int4*)(h0p + u * 16) = *(int4*)(d0buf + u * 16);
                *(int4*)(h1p + u * 16) = *(int4*)(d1buf + u * 16);
            }
        }

        // ---- device-wide step barrier ----
        if (t + 1 < T_SZ) {
            __threadfence();
            __syncthreads();
            if (tid == 0) {
                atomicAdd(&g_bar, 1u);
                const unsigned target = 128u * (unsigned)(t + 1);
                while (*(volatile unsigned*)&g_bar < target) { __nanosleep(64); }
            }
            __syncthreads();
        }
    }
}

// ================= prep kernels =================
// per permuted column p: scale s = max|W[:,n(p)]| / 127  (coalesced over n)
__global__ void prep_scale(const float* __restrict__ W)
{
    const int n = blockIdx.x * blockDim.x + threadIdx.x;   // 0..4095
    if (n >= GATES) return;
    float m = 0.0f;
    for (int k = 0; k < WK; k++)
        m = fmaxf(m, fabsf(W[(size_t)(EMB + k) * GATES + n]));
    const float s = fmaxf(m, 1e-30f) / 127.0f;
    const int q = n >> 10, rem = n & 1023, j = rem >> 5, l = rem & 31;
    const int p = j * 128 + q * 32 + l;
    g_sc[p] = s;
    g_s1[p] = s / 127.0f;
    g_s2[p] = s / 16129.0f;
}

// quantize W (h part) into two s8 digits, permuted N-major
__global__ void prep_w(const float* __restrict__ W)
{
    int idx = blockIdx.x * blockDim.x + threadIdx.x;
    if (idx >= GATES * WK) return;
    const int p  = idx / WK;
    const int k  = idx % WK;
    const int q = (p >> 5) & 3, j = p >> 7, l = p & 31;
    const int n = q * 1024 + j * 32 + l;
    const float w = W[(size_t)(EMB + k) * GATES + n];
    const float x = w / g_sc[p];
    const int e0 = __float2int_rn(x);
    const int e1 = __float2int_rn((x - (float)e0) * 127.0f);
    g_We0[idx] = (int8_t)e0;
    g_We1[idx] = (int8_t)e1;
}

__global__ void prep_misc()
{
    int idx = blockIdx.x * blockDim.x + threadIdx.x;
    if (idx == 0) g_bar = 0u;
    if (idx < B_SZ * HID) {
        g_c[idx] = 0.0f;
        g_hd0[0][idx] = 0;
        g_hd1[0][idx] = 0;
    }
}

// E'[v][p] = embed[v,:] @ W_cell[0:512, n(p)] + b[n] (+1 for f gate)
__global__ __launch_bounds__(256)
void prep_e(const float* __restrict__ A, const float* __restrict__ W,
            const float* __restrict__ bias)
{
    __shared__ float As[16][132];
    __shared__ float Bs[16][128];
    const int tid = threadIdx.x;
    const int bm = blockIdx.y * 128;
    const int bn = blockIdx.x * 128;
    const int K = EMB, N = GATES;

    const int ar0 = tid >> 2, ar1 = ar0 + 64, akq = (tid & 3) * 4;
    const int br0 = tid >> 5, br1 = br0 + 8, bc = (tid & 31) * 4;
    const int tm = (tid >> 4) * 8, tn = (tid & 15) * 8;

    float acc[8][8];
    #pragma unroll
    for (int i = 0; i < 8; i++)
        #pragma unroll
        for (int j = 0; j < 8; j++) acc[i][j] = 0.0f;

    for (int k0 = 0; k0 < K; k0 += 16) {
        const float4 va0 = *(const float4*)(A + (size_t)(bm + ar0) * K + k0 + akq);
        const float4 va1 = *(const float4*)(A + (size_t)(bm + ar1) * K + k0 + akq);
        const float4 vb0 = *(const float4*)(W + (size_t)(k0 + br0) * N + bn + bc);
        const float4 vb1 = *(const float4*)(W + (size_t)(k0 + br1) * N + bn + bc);
        As[akq + 0][ar0] = va0.x; As[akq + 1][ar0] = va0.y;
        As[akq + 2][ar0] = va0.z; As[akq + 3][ar0] = va0.w;
        As[akq + 0][ar1] = va1.x; As[akq + 1][ar1] = va1.y;
        As[akq + 2][ar1] = va1.z; As[akq + 3][ar1] = va1.w;
        *(float4*)&Bs[br0][bc] = vb0;
        *(float4*)&Bs[br1][bc] = vb1;
        __syncthreads();
        #pragma unroll
        for (int kk = 0; kk < 16; kk++) {
            float a[8], b[8];
            *(float4*)&a[0] = *(const float4*)&As[kk][tm];
            *(float4*)&a[4] = *(const float4*)&As[kk][tm + 4];
            *(float4*)&b[0] = *(const float4*)&Bs[kk][tn];
            *(float4*)&b[4] = *(const float4*)&Bs[kk][tn + 4];
            #pragma unroll
            for (int i = 0; i < 8; i++)
                #pragma unroll
                for (int j = 0; j < 8; j++)
                    acc[i][j] = fmaf(a[i], b[j], acc[i][j]);
        }
        __syncthreads();
    }

    const int q = bn >> 10;
    const float fadd = (q == 2) ? 1.0f : 0.0f;
    float bia[8];
    *(float4*)&bia[0] = *(const float4*)(bias + bn + tn);
    *(float4*)&bia[4] = *(const float4*)(bias + bn + tn + 4);
    const int n0 = bn + tn;
    const int j0 = (n0 >> 5) & 31, l0 = n0 & 31;
    const int p0 = j0 * 128 + q * 32 + l0;
    #pragma unroll
    for (int i = 0; i < 8; i++) {
        const int v = bm + tm + i;
        float4 o0, o1;
        o0.x = acc[i][0] + bia[0] + fadd; o0.y = acc[i][1] + bia[1] + fadd;
        o0.z = acc[i][2] + bia[2] + fadd; o0.w = acc[i][3] + bia[3] + fadd;
        o1.x = acc[i][4] + bia[4] + fadd; o1.y = acc[i][5] + bia[5] + fadd;
        o1.z = acc[i][6] + bia[6] + fadd; o1.w = acc[i][7] + bia[7] + fadd;
        float* dst = g_Ep + (size_t)v * GATES + p0;
        *(float4*)(dst)     = o0;
        *(float4*)(dst + 4) = o1;
    }
}

// ================= 64x64-tile SIMT fp32 GEMM (output projections) =================
template<int MODE>   // 0 = A param, 2 = A = g_hf
__global__ __launch_bounds__(256)
void gemm64(const float* __restrict__ A, const float* __restrict__ W,
            const float* __restrict__ bias, float* __restrict__ C,
            int N, int K)
{
    __shared__ float As[16][68];
    __shared__ float Bs[16][64];
    const int tid = threadIdx.x;
    const int bm = blockIdx.y * 64;
    const int bn = blockIdx.x * 64;
    const float* Ab = (MODE == 2) ? (const float*)g_hf : A;

    const int ar = tid >> 2, ak = (tid & 3) * 4;
    const int br = tid >> 4, bc = (tid & 15) * 4;
    const int tm = (tid >> 4) * 4, tn = (tid & 15) * 4;

    float acc[4][4];
    #pragma unroll
    for (int i = 0; i < 4; i++)
        #pragma unroll
        for (int j = 0; j < 4; j++) acc[i][j] = 0.0f;

    for (int k0 = 0; k0 < K; k0 += 16) {
        const float4 va = *(const float4*)(Ab + (size_t)(bm + ar) * K + k0 + ak);
        const float4 vb = *(const float4*)(W + (size_t)(k0 + br) * N + bn + bc);
        As[ak + 0][ar] = va.x; As[ak + 1][ar] = va.y;
        As[ak + 2][ar] = va.z; As[ak + 3][ar] = va.w;
        *(float4*)&Bs[br][bc] = vb;
        __syncthreads();
        #pragma unroll
        for (int kk = 0; kk < 16; kk++) {
            float a[4], b[4];
            *(float4*)&a[0] = *(const float4*)&As[kk][tm];
            *(float4*)&b[0] = *(const float4*)&Bs[kk][tn];
            #pragma unroll
            for (int i = 0; i < 4; i++)
                #pragma unroll
                for (int j = 0; j < 4; j++)
                    acc[i][j] = fmaf(a[i], b[j], acc[i][j]);
        }
        __syncthreads();
    }
    float4 bia = *(const float4*)(bias + bn + tn);
    #pragma unroll
    for (int i = 0; i < 4; i++) {
        float4 o;
        o.x = acc[i][0] + bia.x; o.y = acc[i][1] + bia.y;
        o.z = acc[i][2] + bia.z; o.w = acc[i][3] + bia.w;
        *(float4*)(C + (size_t)(bm + tm + i) * N + bn + tn) = o;
    }
}

// ================= launch =================
extern "C" void kernel_launch(void* const* d_in, const int* in_sizes, int n_in,
                              void* d_out, int out_size)
{
    const float* images  = (const float*)d_in[0];
    const float* embed   = (const float*)d_in[1];
    const float* W_cell  = (const float*)d_in[2];
    const float* b_cell  = (const float*)d_in[3];
    const float* W_img   = (const float*)d_in[4];
    const float* b_img   = (const float*)d_in[5];
    const float* W_hid   = (const float*)d_in[6];
    const float* b_hid   = (const float*)d_in[7];
    const int*   message = (const int*)d_in[8];
    float* out = (float*)d_out;
    (void)in_sizes; (void)n_in; (void)out_size;

    static int smem_set = 0;
    if (!smem_set) {
        cudaFuncSetAttribute(lstm_persist, cudaFuncAttributeMaxDynamicSharedMemorySize, STEP_SMEM);
        smem_set = 1;
    }

    prep_misc<<<(B_SZ * HID + 255) / 256, 256>>>();
    prep_scale<<<GATES / 256, 256>>>(W_cell);
    prep_w<<<(GATES * WK + 255) / 256, 256>>>(W_cell);
    prep_e<<<dim3(GATES / 128, 1024 / 128), 256>>>(embed, W_cell, b_cell);

    gemm64<0><<<dim3(1024 / 64, B_SZ / 64), 256>>>(images, W_img, b_img, out, 1024, 2048);

    lstm_persist<<<dim3(32, 4), 256, STEP_SMEM>>>(message);

    gemm64<2><<<dim3(1024 / 64, B_SZ / 64), 256>>>(nullptr, W_hid, b_hid,
                                                   out + (size_t)B_SZ * HID, 1024, 1024);
}

// round 9
// speedup vs baseline: 3.0018x; 3.0018x over previous
#include <cuda_runtime.h>
#include <cuda_bf16.h>
#include <math.h>
#include <stdint.h>

#define B_SZ   512
#define T_SZ   128
#define HID    1024
#define EMB    512
#define GATES  4096
#define WK     1024      // recurrent K (h only)
#define NCH    16        // chunks of 64 K-elems
#define SEG    16        // steps per segment launch
#define NTHR   512

// ---------------- device scratch (allocation-free) ----------------
__device__ __nv_bfloat16 g_Whi[GATES * WK];      // [p][k'] permuted N-major (h part)
__device__ __nv_bfloat16 g_Wlo[GATES * WK];
__device__ float g_Ep[1024 * GATES];             // E'[vocab][p]: emb@Wx + b (+1 on f)
__device__ __nv_bfloat16 g_hbhi[2][B_SZ * HID];  // double-buffered h (bf16 hi/lo)
__device__ __nv_bfloat16 g_hblo[2][B_SZ * HID];
__device__ float g_hf[B_SZ * HID];               // fp32 h (final projection)
__device__ float g_c[B_SZ * HID];
__device__ unsigned g_bar;                       // device-wide step barrier

// ---------------- helpers ----------------
__device__ __forceinline__ uint32_t smem_u32(const void* p) {
    uint32_t r;
    asm("{ .reg .u64 t; cvta.to.shared.u64 t, %1; cvt.u32.u64 %0, t; }" : "=r"(r) : "l"(p));
    return r;
}
__device__ __forceinline__ void cpa16(uint32_t dst, const void* src) {
    asm volatile("cp.async.cg.shared.global [%0], [%1], 16;" :: "r"(dst), "l"(src) : "memory");
}
#define CP_COMMIT() asm volatile("cp.async.commit_group;" ::: "memory")
#define CP_WAIT2()  asm volatile("cp.async.wait_group 2;" ::: "memory")
#define CP_WAIT1()  asm volatile("cp.async.wait_group 1;" ::: "memory")
#define CP_WAIT0()  asm volatile("cp.async.wait_group 0;" ::: "memory")

#define LDMX4(r, addr) \
    asm volatile("ldmatrix.sync.aligned.m8n8.x4.shared.b16 {%0,%1,%2,%3}, [%4];" \
        : "=r"((r)[0]), "=r"((r)[1]), "=r"((r)[2]), "=r"((r)[3]) : "r"(addr))

#define MMA(acc, a, b0, b1) \
    asm volatile("mma.sync.aligned.m16n8k16.row.col.f32.bf16.bf16.f32 " \
        "{%0,%1,%2,%3}, {%4,%5,%6,%7}, {%8,%9}, {%0,%1,%2,%3};" \
        : "+f"((acc)[0]), "+f"((acc)[1]), "+f"((acc)[2]), "+f"((acc)[3]) \
        : "r"((a)[0]), "r"((a)[1]), "r"((a)[2]), "r"((a)[3]), "r"(b0), "r"(b1))

#define SW(o) ((uint32_t)(o) ^ ((((uint32_t)(o)) >> 3) & 0x70))

__device__ __forceinline__ float sigm(float x) { return 1.0f / (1.0f + __expf(-x)); }
__device__ __forceinline__ float tanh_f(float x) {
    float e = __expf(2.0f * x);
    return 1.0f - 2.0f / (e + 1.0f);
}

// smem: 3 stages; each stage = 4 regions (Ahi/Alo/Bhi/Blo) of 128 rows x 128B
#define OFF_AHI   0
#define OFF_ALO   16384
#define OFF_BHI   32768
#define OFF_BLO   49152
#define STAGE_SZ  65536
#define STEP_SMEM (3 * STAGE_SZ)   // 196608

// ================= LSTM segment: SEG steps, 512 threads, bf16 3-pass =================
__global__ void __launch_bounds__(NTHR, 1)
lstm_seg(const int* __restrict__ message, int t0, unsigned bar_base)
{
    extern __shared__ __align__(1024) char smem[];
    const uint32_t sm = smem_u32(smem);
    const int tid  = threadIdx.x;
    const int lane = tid & 31;
    const int wid  = tid >> 5;              // 0..15
    const int bx   = blockIdx.x;            // n-tile 0..31 (permuted cols)
    const int bm   = blockIdx.y * 128;      // m-tile base row

    // ---- loader addressing: 512 threads, 8 x 16B per chunk each ----
    const int r = tid >> 2;                 // 0..127 tile row
    const int q = tid & 3;                  // 16B quarter
    const char* bWhi = (const char*)(g_Whi + (size_t)(bx * 128 + r) * WK);
    const char* bWlo = (const char*)(g_Wlo + (size_t)(bx * 128 + r) * WK);
    const char* hHi[2] = { (const char*)(g_hbhi[0] + (size_t)(bm + r) * HID),
                           (const char*)(g_hbhi[1] + (size_t)(bm + r) * HID) };
    const char* hLo[2] = { (const char*)(g_hblo[0] + (size_t)(bm + r) * HID),
                           (const char*)(g_hblo[1] + (size_t)(bm + r) * HID) };
    const uint32_t sw0 = SW(r * 128 + q * 16);
    const uint32_t sw1 = SW(r * 128 + 64 + q * 16);
    const int go0 = q * 16, go1 = 64 + q * 16;

    // ---- warp compute layout: 4(M) x 4(N) warps; warp tile 32x32 ----
    const int wm = (wid >> 2) * 32;
    const int wn = (wid & 3) * 32;
    const int aRow = (lane & 15);
    const int aSel = ((lane >> 4) & 1) * 16;
    const int bRowBase = (lane & 7) + ((lane >> 4) & 1) * 8;
    const int bSel = ((lane >> 3) & 1) * 16;

    // ---- epilogue addressing: 4 threads per row, 8 cols each ----
    const int erow  = bm + (tid >> 2);
    const int esub  = tid & 3;
    const int* msgp = message + erow * T_SZ;
    float* crow = g_c + (size_t)erow * HID + bx * 32 + esub * 8;
    float* hrow = g_hf + (size_t)erow * HID + bx * 32 + esub * 8;
    float* smC = (float*)smem;

    #pragma unroll 1
    for (int ts = 0; ts < SEG; ts++) {
        const int t = t0 + ts;
        const char* aHhi = hHi[t & 1];
        const char* aHlo = hLo[t & 1];

        float acc[2][4][4];
        #pragma unroll
        for (int i = 0; i < 2; i++)
            #pragma unroll
            for (int j = 0; j < 4; j++)
                #pragma unroll
                for (int k = 0; k < 4; k++) acc[i][j][k] = 0.0f;

        // ---- prefetch chunks 0,1 into slots 0,1 ----
        #pragma unroll
        for (int c = 0; c < 2; c++) {
            const uint32_t dst = sm + c * STAGE_SZ;
            const int kb = c * 128;
            cpa16(dst + OFF_AHI + sw0, aHhi + kb + go0);
            cpa16(dst + OFF_AHI + sw1, aHhi + kb + go1);
            cpa16(dst + OFF_ALO + sw0, aHlo + kb + go0);
            cpa16(dst + OFF_ALO + sw1, aHlo + kb + go1);
            cpa16(dst + OFF_BHI + sw0, bWhi + kb + go0);
            cpa16(dst + OFF_BHI + sw1, bWhi + kb + go1);
            cpa16(dst + OFF_BLO + sw0, bWlo + kb + go0);
            cpa16(dst + OFF_BLO + sw1, bWlo + kb + go1);
            CP_COMMIT();
        }

        int sc = 0, sp = 2;
        #pragma unroll 1
        for (int c = 0; c < NCH; c++) {
            if (c < NCH - 2)      { CP_WAIT2(); }
            else if (c == NCH - 2){ CP_WAIT1(); }
            else                  { CP_WAIT0(); }
            __syncthreads();   // chunk c visible; all warps done with slot sp

            if (c + 2 < NCH) {
                const uint32_t dst = sm + sp * STAGE_SZ;
                const int kb = (c + 2) * 128;
                cpa16(dst + OFF_AHI + sw0, aHhi + kb + go0);
                cpa16(dst + OFF_AHI + sw1, aHhi + kb + go1);
                cpa16(dst + OFF_ALO + sw0, aHlo + kb + go0);
                cpa16(dst + OFF_ALO + sw1, aHlo + kb + go1);
                cpa16(dst + OFF_BHI + sw0, bWhi + kb + go0);
                cpa16(dst + OFF_BHI + sw1, bWhi + kb + go1);
                cpa16(dst + OFF_BLO + sw0, bWlo + kb + go0);
                cpa16(dst + OFF_BLO + sw1, bWlo + kb + go1);
                CP_COMMIT();
            }

            const uint32_t stage = sm + sc * STAGE_SZ;
            #pragma unroll
            for (int k16 = 0; k16 < 4; k16++) {
                const int kb = k16 * 32;
                uint32_t ah[2][4], al[2][4], bh[2][4], bl[2][4];
                #pragma unroll
                for (int mi = 0; mi < 2; mi++) {
                    const uint32_t ao = SW((wm + mi * 16 + aRow) * 128 + kb + aSel);
                    LDMX4(ah[mi], stage + OFF_AHI + ao);
                    LDMX4(al[mi], stage + OFF_ALO + ao);
                }
                #pragma unroll
                for (int nj = 0; nj < 2; nj++) {
                    const uint32_t bo = SW((wn + nj * 16 + bRowBase) * 128 + kb + bSel);
                    LDMX4(bh[nj], stage + OFF_BHI + bo);
                    LDMX4(bl[nj], stage + OFF_BLO + bo);
                }
                #pragma unroll
                for (int mi = 0; mi < 2; mi++) {
                    #pragma unroll
                    for (int n8 = 0; n8 < 4; n8++) {
                        const uint32_t bh0 = bh[n8 >> 1][(n8 & 1) * 2];
                        const uint32_t bh1 = bh[n8 >> 1][(n8 & 1) * 2 + 1];
                        const uint32_t bl0 = bl[n8 >> 1][(n8 & 1) * 2];
                        const uint32_t bl1 = bl[n8 >> 1][(n8 & 1) * 2 + 1];
                        MMA(acc[mi][n8], ah[mi], bh0, bh1);
                        MMA(acc[mi][n8], al[mi], bh0, bh1);
                        MMA(acc[mi][n8], ah[mi], bl0, bl1);
                    }
                }
            }
            sc = (sc == 2) ? 0 : sc + 1;
            sp = (sp == 2) ? 0 : sp + 1;
        }

        // ---- stage accumulators to smem (fp32, stride 132) ----
        __syncthreads();
        #pragma unroll
        for (int mi = 0; mi < 2; mi++) {
            #pragma unroll
            for (int n8 = 0; n8 < 4; n8++) {
                const int row = wm + mi * 16 + (lane >> 2);
                const int col = wn + n8 * 8 + (lane & 3) * 2;
                smC[row * 132 + col]           = acc[mi][n8][0];
                smC[row * 132 + col + 1]       = acc[mi][n8][1];
                smC[(row + 8) * 132 + col]     = acc[mi][n8][2];
                smC[(row + 8) * 132 + col + 1] = acc[mi][n8][3];
            }
        }
        __syncthreads();

        // ---- fused epilogue: 4 threads per row, 8 elems each ----
        {
            const int msg = msgp[t];
            const float* cr = smC + (tid >> 2) * 132 + esub * 8;
            const float* ep = g_Ep + (size_t)msg * GATES + bx * 128 + esub * 8;
            __nv_bfloat16* hh = g_hbhi[(t + 1) & 1] + (size_t)erow * HID + bx * 32 + esub * 8;
            __nv_bfloat16* hl = g_hblo[(t + 1) & 1] + (size_t)erow * HID + bx * 32 + esub * 8;
            __nv_bfloat16 hhb[8], hlb[8];
            float hvb[8];
            #pragma unroll
            for (int l = 0; l < 8; l++) {
                const float iv = cr[l]      + ep[l];
                const float gv = cr[32 + l] + ep[32 + l];
                const float fv = cr[64 + l] + ep[64 + l];   // +1 folded
                const float ov = cr[96 + l] + ep[96 + l];
                const float cc = sigm(fv) * crow[l] + sigm(iv) * tanh_f(gv);
                const float hv = sigm(ov) * tanh_f(cc);
                crow[l] = cc;
                hvb[l] = hv;
                const __nv_bfloat16 hi = __float2bfloat16(hv);
                hhb[l] = hi;
                hlb[l] = __float2bfloat16(hv - __bfloat162float(hi));
            }
            *(int4*)hh = *(int4*)hhb;
            *(int4*)hl = *(int4*)hlb;
            if (t == T_SZ - 1) {
                *(float4*)(hrow)     = *(float4*)(hvb);
                *(float4*)(hrow + 4) = *(float4*)(hvb + 4);
            }
        }

        // ---- device-wide step barrier (monotonic round index per launch) ----
        if (ts + 1 < SEG) {
            __threadfence();
            __syncthreads();
            if (tid == 0) {
                atomicAdd(&g_bar, 1u);
                const unsigned target = bar_base + 128u * (unsigned)(ts + 1);
                while (*(volatile unsigned*)&g_bar < target) { __nanosleep(64); }
            }
            __syncthreads();
        }
    }
}

// ================= prep kernels =================
__global__ void prep_w(const float* __restrict__ W)
{
    int idx = blockIdx.x * blockDim.x + threadIdx.x;
    if (idx >= GATES * WK) return;
    const int p  = idx / WK;
    const int k  = idx % WK;
    const int q = (p >> 5) & 3, j = p >> 7, l = p & 31;
    const int n = q * 1024 + j * 32 + l;
    const float w = W[(size_t)(EMB + k) * GATES + n];
    const __nv_bfloat16 hi = __float2bfloat16(w);
    g_Whi[idx] = hi;
    g_Wlo[idx] = __float2bfloat16(w - __bfloat162float(hi));
}

__global__ void prep_misc()
{
    int idx = blockIdx.x * blockDim.x + threadIdx.x;
    if (idx == 0) g_bar = 0u;
    if (idx < B_SZ * HID) {
        g_c[idx] = 0.0f;
        g_hbhi[0][idx] = __float2bfloat16(0.0f);
        g_hblo[0][idx] = __float2bfloat16(0.0f);
    }
}

// E'[v][p] = embed[v,:] @ W_cell[0:512, n(p)] + b[n] (+1 for f gate)
__global__ __launch_bounds__(256)
void prep_e(const float* __restrict__ A, const float* __restrict__ W,
            const float* __restrict__ bias)
{
    __shared__ float As[16][132];
    __shared__ float Bs[16][128];
    const int tid = threadIdx.x;
    const int bm = blockIdx.y * 128;
    const int bn = blockIdx.x * 128;
    const int K = EMB, N = GATES;

    const int ar0 = tid >> 2, ar1 = ar0 + 64, akq = (tid & 3) * 4;
    const int br0 = tid >> 5, br1 = br0 + 8, bc = (tid & 31) * 4;
    const int tm = (tid >> 4) * 8, tn = (tid & 15) * 8;

    float acc[8][8];
    #pragma unroll
    for (int i = 0; i < 8; i++)
        #pragma unroll
        for (int j = 0; j < 8; j++) acc[i][j] = 0.0f;

    for (int k0 = 0; k0 < K; k0 += 16) {
        const float4 va0 = *(const float4*)(A + (size_t)(bm + ar0) * K + k0 + akq);
        const float4 va1 = *(const float4*)(A + (size_t)(bm + ar1) * K + k0 + akq);
        const float4 vb0 = *(const float4*)(W + (size_t)(k0 + br0) * N + bn + bc);
        const float4 vb1 = *(const float4*)(W + (size_t)(k0 + br1) * N + bn + bc);
        As[akq + 0][ar0] = va0.x; As[akq + 1][ar0] = va0.y;
        As[akq + 2][ar0] = va0.z; As[akq + 3][ar0] = va0.w;
        As[akq + 0][ar1] = va1.x; As[akq + 1][ar1] = va1.y;
        As[akq + 2][ar1] = va1.z; As[akq + 3][ar1] = va1.w;
        *(float4*)&Bs[br0][bc] = vb0;
        *(float4*)&Bs[br1][bc] = vb1;
        __syncthreads();
        #pragma unroll
        for (int kk = 0; kk < 16; kk++) {
            float a[8], b[8];
            *(float4*)&a[0] = *(const float4*)&As[kk][tm];
            *(float4*)&a[4] = *(const float4*)&As[kk][tm + 4];
            *(float4*)&b[0] = *(const float4*)&Bs[kk][tn];
            *(float4*)&b[4] = *(const float4*)&Bs[kk][tn + 4];
            #pragma unroll
            for (int i = 0; i < 8; i++)
                #pragma unroll
                for (int j = 0; j < 8; j++)
                    acc[i][j] = fmaf(a[i], b[j], acc[i][j]);
        }
        __syncthreads();
    }

    const int q = bn >> 10;
    const float fadd = (q == 2) ? 1.0f : 0.0f;
    float bia[8];
    *(float4*)&bia[0] = *(const float4*)(bias + bn + tn);
    *(float4*)&bia[4] = *(const float4*)(bias + bn + tn + 4);
    const int n0 = bn + tn;
    const int j0 = (n0 >> 5) & 31, l0 = n0 & 31;
    const int p0 = j0 * 128 + q * 32 + l0;
    #pragma unroll
    for (int i = 0; i < 8; i++) {
        const int v = bm + tm + i;
        float4 o0, o1;
        o0.x = acc[i][0] + bia[0] + fadd; o0.y = acc[i][1] + bia[1] + fadd;
        o0.z = acc[i][2] + bia[2] + fadd; o0.w = acc[i][3] + bia[3] + fadd;
        o1.x = acc[i][4] + bia[4] + fadd; o1.y = acc[i][5] + bia[5] + fadd;
        o1.z = acc[i][6] + bia[6] + fadd; o1.w = acc[i][7] + bia[7] + fadd;
        float* dst = g_Ep + (size_t)v * GATES + p0;
        *(float4*)(dst)     = o0;
        *(float4*)(dst + 4) = o1;
    }
}

// ================= 64x64-tile SIMT fp32 GEMM (output projections) =================
template<int MODE>   // 0 = A param, 2 = A = g_hf
__global__ __launch_bounds__(256)
void gemm64(const float* __restrict__ A, const float* __restrict__ W,
            const float* __restrict__ bias, float* __restrict__ C,
            int N, int K)
{
    __shared__ float As[16][68];
    __shared__ float Bs[16][64];
    const int tid = threadIdx.x;
    const int bm = blockIdx.y * 64;
    const int bn = blockIdx.x * 64;
    const float* Ab = (MODE == 2) ? (const float*)g_hf : A;

    const int ar = tid >> 2, ak = (tid & 3) * 4;
    const int br = tid >> 4, bc = (tid & 15) * 4;
    const int tm = (tid >> 4) * 4, tn = (tid & 15) * 4;

    float acc[4][4];
    #pragma unroll
    for (int i = 0; i < 4; i++)
        #pragma unroll
        for (int j = 0; j < 4; j++) acc[i][j] = 0.0f;

    for (int k0 = 0; k0 < K; k0 += 16) {
        const float4 va = *(const float4*)(Ab + (size_t)(bm + ar) * K + k0 + ak);
        const float4 vb = *(const float4*)(W + (size_t)(k0 + br) * N + bn + bc);
        As[ak + 0][ar] = va.x; As[ak + 1][ar] = va.y;
        As[ak + 2][ar] = va.z; As[ak + 3][ar] = va.w;
        *(float4*)&Bs[br][bc] = vb;
        __syncthreads();
        #pragma unroll
        for (int kk = 0; kk < 16; kk++) {
            float a[4], b[4];
            *(float4*)&a[0] = *(const float4*)&As[kk][tm];
            *(float4*)&b[0] = *(const float4*)&Bs[kk][tn];
            #pragma unroll
            for (int i = 0; i < 4; i++)
                #pragma unroll
                for (int j = 0; j < 4; j++)
                    acc[i][j] = fmaf(a[i], b[j], acc[i][j]);
        }
        __syncthreads();
    }
    float4 bia = *(const float4*)(bias + bn + tn);
    #pragma unroll
    for (int i = 0; i < 4; i++) {
        float4 o;
        o.x = acc[i][0] + bia.x; o.y = acc[i][1] + bia.y;
        o.z = acc[i][2] + bia.z; o.w = acc[i][3] + bia.w;
        *(float4*)(C + (size_t)(bm + tm + i) * N + bn + tn) = o;
    }
}

// ================= launch =================
extern "C" void kernel_launch(void* const* d_in, const int* in_sizes, int n_in,
                              void* d_out, int out_size)
{
    const float* images  = (const float*)d_in[0];
    const float* embed   = (const float*)d_in[1];
    const float* W_cell  = (const float*)d_in[2];
    const float* b_cell  = (const float*)d_in[3];
    const float* W_img   = (const float*)d_in[4];
    const float* b_img   = (const float*)d_in[5];
    const float* W_hid   = (const float*)d_in[6];
    const float* b_hid   = (const float*)d_in[7];
    const int*   message = (const int*)d_in[8];
    float* out = (float*)d_out;
    (void)in_sizes; (void)n_in; (void)out_size;

    static int smem_set = 0;
    if (!smem_set) {
        cudaFuncSetAttribute(lstm_seg, cudaFuncAttributeMaxDynamicSharedMemorySize, STEP_SMEM);
        smem_set = 1;
    }

    prep_misc<<<(B_SZ * HID + 255) / 256, 256>>>();
    prep_w<<<(GATES * WK + 255) / 256, 256>>>(W_cell);
    prep_e<<<dim3(GATES / 128, 1024 / 128), 256>>>(embed, W_cell, b_cell);

    gemm64<0><<<dim3(1024 / 64, B_SZ / 64), 256>>>(images, W_img, b_img, out, 1024, 2048);

    for (int t0 = 0; t0 < T_SZ; t0 += SEG) {
        const unsigned bar_base = 128u * (unsigned)(SEG - 1) * (unsigned)(t0 / SEG);
        lstm_seg<<<dim3(32, 4), NTHR, STEP_SMEM>>>(message, t0, bar_base);
    }

    gemm64<2><<<dim3(1024 / 64, B_SZ / 64), 256>>>(nullptr, W_hid, b_hid,
                                                   out + (size_t)B_SZ * HID, 1024, 1024);
}

// round 10
// speedup vs baseline: 3.0117x; 1.0033x over previous
#include <cuda_runtime.h>
#include <cuda_bf16.h>
#include <math.h>
#include <stdint.h>

#define B_SZ   512
#define T_SZ   128
#define HID    1024
#define EMB    512
#define GATES  4096
#define WK     1024      // recurrent K (h only)
#define NCH    16        // chunks of 64 K-elems
#define SEG    16        // steps per segment launch
#define NTHR   512

// ---------------- device scratch (allocation-free) ----------------
__device__ __nv_bfloat16 g_Whi[GATES * WK];      // [p][k'] permuted N-major (h part)
__device__ __nv_bfloat16 g_Wlo[GATES * WK];
__device__ float g_Ep[1024 * GATES];             // E'[vocab][p]: emb@Wx + b (+1 on f)
__device__ __nv_bfloat16 g_hbhi[2][B_SZ * HID];  // double-buffered h (bf16 hi/lo)
__device__ __nv_bfloat16 g_hblo[2][B_SZ * HID];
__device__ float g_hf[B_SZ * HID];               // fp32 h (final projection)
__device__ float g_c[B_SZ * HID];
__device__ unsigned g_bar[128];                  // 4 m-group barriers, stride 32

// ---------------- helpers ----------------
__device__ __forceinline__ uint32_t smem_u32(const void* p) {
    uint32_t r;
    asm("{ .reg .u64 t; cvta.to.shared.u64 t, %1; cvt.u32.u64 %0, t; }" : "=r"(r) : "l"(p));
    return r;
}
__device__ __forceinline__ void cpa16(uint32_t dst, const void* src) {
    asm volatile("cp.async.cg.shared.global [%0], [%1], 16;" :: "r"(dst), "l"(src) : "memory");
}
#define CP_COMMIT() asm volatile("cp.async.commit_group;" ::: "memory")
#define CP_WAIT1()  asm volatile("cp.async.wait_group 1;" ::: "memory")
#define CP_WAIT0()  asm volatile("cp.async.wait_group 0;" ::: "memory")

#define LDMX4(r, addr) \
    asm volatile("ldmatrix.sync.aligned.m8n8.x4.shared.b16 {%0,%1,%2,%3}, [%4];" \
        : "=r"((r)[0]), "=r"((r)[1]), "=r"((r)[2]), "=r"((r)[3]) : "r"(addr))

#define MMA(acc, a, b0, b1) \
    asm volatile("mma.sync.aligned.m16n8k16.row.col.f32.bf16.bf16.f32 " \
        "{%0,%1,%2,%3}, {%4,%5,%6,%7}, {%8,%9}, {%0,%1,%2,%3};" \
        : "+f"((acc)[0]), "+f"((acc)[1]), "+f"((acc)[2]), "+f"((acc)[3]) \
        : "r"((a)[0]), "r"((a)[1]), "r"((a)[2]), "r"((a)[3]), "r"(b0), "r"(b1))

#define SW(o) ((uint32_t)(o) ^ ((((uint32_t)(o)) >> 3) & 0x70))

__device__ __forceinline__ float sigm(float x) { return 1.0f / (1.0f + __expf(-x)); }
__device__ __forceinline__ float tanh_f(float x) {
    float e = __expf(2.0f * x);
    return 1.0f - 2.0f / (e + 1.0f);
}

// smem: 3 stages; each stage = 4 regions (Ahi/Alo/Bhi/Blo) of 128 rows x 128B.
// Accumulator staging area smC overlaps slot 1 (+2KB of slot 2's A region) —
// disjoint from slot0/slot2 B regions used by the pre-barrier weight prefetch.
#define OFF_AHI   0
#define OFF_ALO   16384
#define OFF_BHI   32768
#define OFF_BLO   49152
#define STAGE_SZ  65536
#define STEP_SMEM (3 * STAGE_SZ)   // 196608

// A/B prefetch of one 64-K-elem chunk (128B per row), this thread's 2x16B share
#define PREF_A(base, kb) do { \
    cpa16((base) + OFF_AHI + sw0, aHhi + (kb) + go0); \
    cpa16((base) + OFF_AHI + sw1, aHhi + (kb) + go1); \
    cpa16((base) + OFF_ALO + sw0, aHlo + (kb) + go0); \
    cpa16((base) + OFF_ALO + sw1, aHlo + (kb) + go1); \
} while (0)
#define PREF_B(base, kb) do { \
    cpa16((base) + OFF_BHI + sw0, bWhi + (kb) + go0); \
    cpa16((base) + OFF_BHI + sw1, bWhi + (kb) + go1); \
    cpa16((base) + OFF_BLO + sw0, bWlo + (kb) + go0); \
    cpa16((base) + OFF_BLO + sw1, bWlo + (kb) + go1); \
} while (0)

// ================= LSTM segment: SEG steps, 512 threads, bf16 3-pass =================
__global__ void __launch_bounds__(NTHR, 1)
lstm_seg(const int* __restrict__ message, int t0, unsigned bar_base)
{
    extern __shared__ __align__(1024) char smem[];
    const uint32_t sm = smem_u32(smem);
    const int tid  = threadIdx.x;
    const int lane = tid & 31;
    const int wid  = tid >> 5;              // 0..15
    const int bx   = blockIdx.x;            // n-tile 0..31 (permuted cols)
    const int bm   = blockIdx.y * 128;      // m-tile base row

    // ---- loader addressing: 512 threads, 8 x 16B per chunk each ----
    const int r = tid >> 2;                 // 0..127 tile row
    const int q = tid & 3;                  // 16B quarter
    const char* bWhi = (const char*)(g_Whi + (size_t)(bx * 128 + r) * WK);
    const char* bWlo = (const char*)(g_Wlo + (size_t)(bx * 128 + r) * WK);
    const char* hHi[2] = { (const char*)(g_hbhi[0] + (size_t)(bm + r) * HID),
                           (const char*)(g_hbhi[1] + (size_t)(bm + r) * HID) };
    const char* hLo[2] = { (const char*)(g_hblo[0] + (size_t)(bm + r) * HID),
                           (const char*)(g_hblo[1] + (size_t)(bm + r) * HID) };
    const uint32_t sw0 = SW(r * 128 + q * 16);
    const uint32_t sw1 = SW(r * 128 + 64 + q * 16);
    const int go0 = q * 16, go1 = 64 + q * 16;

    // ---- warp compute layout: 4(M) x 4(N) warps; warp tile 32x32 ----
    const int wm = (wid >> 2) * 32;
    const int wn = (wid & 3) * 32;
    const int aRow = (lane & 15);
    const int aSel = ((lane >> 4) & 1) * 16;
    const int bRowBase = (lane & 7) + ((lane >> 4) & 1) * 8;
    const int bSel = ((lane >> 3) & 1) * 16;

    // ---- epilogue addressing: 4 threads per row, 8 cols each ----
    const int erow  = bm + (tid >> 2);
    const int esub  = tid & 3;
    const int* msgp = message + erow * T_SZ;
    float* crow = g_c + (size_t)erow * HID + bx * 32 + esub * 8;
    float* hrow = g_hf + (size_t)erow * HID + bx * 32 + esub * 8;
    float* smC = (float*)(smem + STAGE_SZ);   // overlaps slot 1 (safe by schedule)

    // ---- initial pre-barrier weight prefetch (chunks 0 and 2; W only) ----
    PREF_B(sm, 0);
    PREF_B(sm + 2 * STAGE_SZ, 2 * 128);

    #pragma unroll 1
    for (int ts = 0; ts < SEG; ts++) {
        const int t = t0 + ts;
        const char* aHhi = hHi[t & 1];
        const char* aHlo = hLo[t & 1];

        float acc[2][4][4];
        #pragma unroll
        for (int i = 0; i < 2; i++)
            #pragma unroll
            for (int j = 0; j < 4; j++)
                #pragma unroll
                for (int k = 0; k < 4; k++) acc[i][j][k] = 0.0f;

        // ---- post-barrier: A chunk 0 (group also carries B0,B2), then chunk 1 A+B ----
        PREF_A(sm, 0);
        CP_COMMIT();
        PREF_A(sm + STAGE_SZ, 128);
        PREF_B(sm + STAGE_SZ, 128);
        CP_COMMIT();

        int sc = 0, sp = 2;
        #pragma unroll 1
        for (int c = 0; c < NCH; c++) {
            if (c < NCH - 1) { CP_WAIT1(); } else { CP_WAIT0(); }
            __syncthreads();   // chunk c visible to all; all warps done with slot sp

            if (c + 2 < NCH) {
                const uint32_t dst = sm + sp * STAGE_SZ;
                const int kb = (c + 2) * 128;
                PREF_A(dst, kb);
                if (c != 0) PREF_B(dst, kb);   // c==0: chunk2's B preloaded pre-barrier
                CP_COMMIT();
            }

            const uint32_t stage = sm + sc * STAGE_SZ;
            #pragma unroll
            for (int k16 = 0; k16 < 4; k16++) {
                const int kb = k16 * 32;
                uint32_t ah[2][4], al[2][4], bh[2][4], bl[2][4];
                #pragma unroll
                for (int mi = 0; mi < 2; mi++) {
                    const uint32_t ao = SW((wm + mi * 16 + aRow) * 128 + kb + aSel);
                    LDMX4(ah[mi], stage + OFF_AHI + ao);
                    LDMX4(al[mi], stage + OFF_ALO + ao);
                }
                #pragma unroll
                for (int nj = 0; nj < 2; nj++) {
                    const uint32_t bo = SW((wn + nj * 16 + bRowBase) * 128 + kb + bSel);
                    LDMX4(bh[nj], stage + OFF_BHI + bo);
                    LDMX4(bl[nj], stage + OFF_BLO + bo);
                }
                #pragma unroll
                for (int mi = 0; mi < 2; mi++) {
                    #pragma unroll
                    for (int n8 = 0; n8 < 4; n8++) {
                        const uint32_t bh0 = bh[n8 >> 1][(n8 & 1) * 2];
                        const uint32_t bh1 = bh[n8 >> 1][(n8 & 1) * 2 + 1];
                        const uint32_t bl0 = bl[n8 >> 1][(n8 & 1) * 2];
                        const uint32_t bl1 = bl[n8 >> 1][(n8 & 1) * 2 + 1];
                        MMA(acc[mi][n8], ah[mi], bh0, bh1);
                        MMA(acc[mi][n8], al[mi], bh0, bh1);
                        MMA(acc[mi][n8], ah[mi], bl0, bl1);
                    }
                }
            }
            sc = (sc == 2) ? 0 : sc + 1;
            sp = (sp == 2) ? 0 : sp + 1;
        }

        __syncthreads();   // all warps done with all stage slots

        // ---- pre-barrier weight prefetch for NEXT step (slots 0,2 B-regions free) ----
        if (ts + 1 < SEG) {
            PREF_B(sm, 0);
            PREF_B(sm + 2 * STAGE_SZ, 2 * 128);
        }

        // ---- stage accumulators to smC (fp32, stride 132) ----
        #pragma unroll
        for (int mi = 0; mi < 2; mi++) {
            #pragma unroll
            for (int n8 = 0; n8 < 4; n8++) {
                const int row = wm + mi * 16 + (lane >> 2);
                const int col = wn + n8 * 8 + (lane & 3) * 2;
                smC[row * 132 + col]           = acc[mi][n8][0];
                smC[row * 132 + col + 1]       = acc[mi][n8][1];
                smC[(row + 8) * 132 + col]     = acc[mi][n8][2];
                smC[(row + 8) * 132 + col + 1] = acc[mi][n8][3];
            }
        }
        __syncthreads();

        // ---- fused epilogue: 4 threads per row, 8 elems each ----
        {
            const int msg = msgp[t];
            const float* cr = smC + (tid >> 2) * 132 + esub * 8;
            const float* ep = g_Ep + (size_t)msg * GATES + bx * 128 + esub * 8;
            __nv_bfloat16* hh = g_hbhi[(t + 1) & 1] + (size_t)erow * HID + bx * 32 + esub * 8;
            __nv_bfloat16* hl = g_hblo[(t + 1) & 1] + (size_t)erow * HID + bx * 32 + esub * 8;
            __nv_bfloat16 hhb[8], hlb[8];
            float hvb[8];
            #pragma unroll
            for (int l = 0; l < 8; l++) {
                const float iv = cr[l]      + ep[l];
                const float gv = cr[32 + l] + ep[32 + l];
                const float fv = cr[64 + l] + ep[64 + l];   // +1 folded
                const float ov = cr[96 + l] + ep[96 + l];
                const float cc = sigm(fv) * crow[l] + sigm(iv) * tanh_f(gv);
                const float hv = sigm(ov) * tanh_f(cc);
                crow[l] = cc;
                hvb[l] = hv;
                const __nv_bfloat16 hi = __float2bfloat16(hv);
                hhb[l] = hi;
                hlb[l] = __float2bfloat16(hv - __bfloat162float(hi));
            }
            *(int4*)hh = *(int4*)hhb;
            *(int4*)hl = *(int4*)hlb;
            if (t == T_SZ - 1) {
                *(float4*)(hrow)     = *(float4*)(hvb);
                *(float4*)(hrow + 4) = *(float4*)(hvb + 4);
            }
        }

        // ---- per-m-group barrier (32 CTAs sharing this bm) ----
        if (ts + 1 < SEG) {
            __threadfence();
            __syncthreads();
            if (tid == 0) {
                unsigned* bar = g_bar + (blockIdx.y << 5);
                atomicAdd(bar, 1u);
                const unsigned target = bar_base + 32u * (unsigned)(ts + 1);
                while (*(volatile unsigned*)bar < target) { __nanosleep(64); }
            }
            __syncthreads();
        }
    }
}

// ================= prep kernels =================
__global__ void prep_w(const float* __restrict__ W)
{
    int idx = blockIdx.x * blockDim.x + threadIdx.x;
    if (idx >= GATES * WK) return;
    const int p  = idx / WK;
    const int k  = idx % WK;
    const int q = (p >> 5) & 3, j = p >> 7, l = p & 31;
    const int n = q * 1024 + j * 32 + l;
    const float w = W[(size_t)(EMB + k) * GATES + n];
    const __nv_bfloat16 hi = __float2bfloat16(w);
    g_Whi[idx] = hi;
    g_Wlo[idx] = __float2bfloat16(w - __bfloat162float(hi));
}

__global__ void prep_misc()
{
    int idx = blockIdx.x * blockDim.x + threadIdx.x;
    if (idx < 128) g_bar[idx] = 0u;
    if (idx < B_SZ * HID) {
        g_c[idx] = 0.0f;
        g_hbhi[0][idx] = __float2bfloat16(0.0f);
        g_hblo[0][idx] = __float2bfloat16(0.0f);
    }
}

// E'[v][p] = embed[v,:] @ W_cell[0:512, n(p)] + b[n] (+1 for f gate)
__global__ __launch_bounds__(256)
void prep_e(const float* __restrict__ A, const float* __restrict__ W,
            const float* __restrict__ bias)
{
    __shared__ float As[16][132];
    __shared__ float Bs[16][128];
    const int tid = threadIdx.x;
    const int bm = blockIdx.y * 128;
    const int bn = blockIdx.x * 128;
    const int K = EMB, N = GATES;

    const int ar0 = tid >> 2, ar1 = ar0 + 64, akq = (tid & 3) * 4;
    const int br0 = tid >> 5, br1 = br0 + 8, bc = (tid & 31) * 4;
    const int tm = (tid >> 4) * 8, tn = (tid & 15) * 8;

    float acc[8][8];
    #pragma unroll
    for (int i = 0; i < 8; i++)
        #pragma unroll
        for (int j = 0; j < 8; j++) acc[i][j] = 0.0f;

    for (int k0 = 0; k0 < K; k0 += 16) {
        const float4 va0 = *(const float4*)(A + (size_t)(bm + ar0) * K + k0 + akq);
        const float4 va1 = *(const float4*)(A + (size_t)(bm + ar1) * K + k0 + akq);
        const float4 vb0 = *(const float4*)(W + (size_t)(k0 + br0) * N + bn + bc);
        const float4 vb1 = *(const float4*)(W + (size_t)(k0 + br1) * N + bn + bc);
        As[akq + 0][ar0] = va0.x; As[akq + 1][ar0] = va0.y;
        As[akq + 2][ar0] = va0.z; As[akq + 3][ar0] = va0.w;
        As[akq + 0][ar1] = va1.x; As[akq + 1][ar1] = va1.y;
        As[akq + 2][ar1] = va1.z; As[akq + 3][ar1] = va1.w;
        *(float4*)&Bs[br0][bc] = vb0;
        *(float4*)&Bs[br1][bc] = vb1;
        __syncthreads();
        #pragma unroll
        for (int kk = 0; kk < 16; kk++) {
            float a[8], b[8];
            *(float4*)&a[0] = *(const float4*)&As[kk][tm];
            *(float4*)&a[4] = *(const float4*)&As[kk][tm + 4];
            *(float4*)&b[0] = *(const float4*)&Bs[kk][tn];
            *(float4*)&b[4] = *(const float4*)&Bs[kk][tn + 4];
            #pragma unroll
            for (int i = 0; i < 8; i++)
                #pragma unroll
                for (int j = 0; j < 8; j++)
                    acc[i][j] = fmaf(a[i], b[j], acc[i][j]);
        }
        __syncthreads();
    }

    const int q = bn >> 10;
    const float fadd = (q == 2) ? 1.0f : 0.0f;
    float bia[8];
    *(float4*)&bia[0] = *(const float4*)(bias + bn + tn);
    *(float4*)&bia[4] = *(const float4*)(bias + bn + tn + 4);
    const int n0 = bn + tn;
    const int j0 = (n0 >> 5) & 31, l0 = n0 & 31;
    const int p0 = j0 * 128 + q * 32 + l0;
    #pragma unroll
    for (int i = 0; i < 8; i++) {
        const int v = bm + tm + i;
        float4 o0, o1;
        o0.x = acc[i][0] + bia[0] + fadd; o0.y = acc[i][1] + bia[1] + fadd;
        o0.z = acc[i][2] + bia[2] + fadd; o0.w = acc[i][3] + bia[3] + fadd;
        o1.x = acc[i][4] + bia[4] + fadd; o1.y = acc[i][5] + bia[5] + fadd;
        o1.z = acc[i][6] + bia[6] + fadd; o1.w = acc[i][7] + bia[7] + fadd;
        float* dst = g_Ep + (size_t)v * GATES + p0;
        *(float4*)(dst)     = o0;
        *(float4*)(dst + 4) = o1;
    }
}

// ================= 64x64-tile SIMT fp32 GEMM (output projections) =================
template<int MODE>   // 0 = A param, 2 = A = g_hf
__global__ __launch_bounds__(256)
void gemm64(const float* __restrict__ A, const float* __restrict__ W,
            const float* __restrict__ bias, float* __restrict__ C,
            int N, int K)
{
    __shared__ float As[16][68];
    __shared__ float Bs[16][64];
    const int tid = threadIdx.x;
    const int bm = blockIdx.y * 64;
    const int bn = blockIdx.x * 64;
    const float* Ab = (MODE == 2) ? (const float*)g_hf : A;

    const int ar = tid >> 2, ak = (tid & 3) * 4;
    const int br = tid >> 4, bc = (tid & 15) * 4;
    const int tm = (tid >> 4) * 4, tn = (tid & 15) * 4;

    float acc[4][4];
    #pragma unroll
    for (int i = 0; i < 4; i++)
        #pragma unroll
        for (int j = 0; j < 4; j++) acc[i][j] = 0.0f;

    for (int k0 = 0; k0 < K; k0 += 16) {
        const float4 va = *(const float4*)(Ab + (size_t)(bm + ar) * K + k0 + ak);
        const float4 vb = *(const float4*)(W + (size_t)(k0 + br) * N + bn + bc);
        As[ak + 0][ar] = va.x; As[ak + 1][ar] = va.y;
        As[ak + 2][ar] = va.z; As[ak + 3][ar] = va.w;
        *(float4*)&Bs[br][bc] = vb;
        __syncthreads();
        #pragma unroll
        for (int kk = 0; kk < 16; kk++) {
            float a[4], b[4];
            *(float4*)&a[0] = *(const float4*)&As[kk][tm];
            *(float4*)&b[0] = *(const float4*)&Bs[kk][tn];
            #pragma unroll
            for (int i = 0; i < 4; i++)
                #pragma unroll
                for (int j = 0; j < 4; j++)
                    acc[i][j] = fmaf(a[i], b[j], acc[i][j]);
        }
        __syncthreads();
    }
    float4 bia = *(const float4*)(bias + bn + tn);
    #pragma unroll
    for (int i = 0; i < 4; i++) {
        float4 o;
        o.x = acc[i][0] + bia.x; o.y = acc[i][1] + bia.y;
        o.z = acc[i][2] + bia.z; o.w = acc[i][3] + bia.w;
        *(float4*)(C + (size_t)(bm + tm + i) * N + bn + tn) = o;
    }
}

// ================= launch =================
extern "C" void kernel_launch(void* const* d_in, const int* in_sizes, int n_in,
                              void* d_out, int out_size)
{
    const float* images  = (const float*)d_in[0];
    const float* embed   = (const float*)d_in[1];
    const float* W_cell  = (const float*)d_in[2];
    const float* b_cell  = (const float*)d_in[3];
    const float* W_img   = (const float*)d_in[4];
    const float* b_img   = (const float*)d_in[5];
    const float* W_hid   = (const float*)d_in[6];
    const float* b_hid   = (const float*)d_in[7];
    const int*   message = (const int*)d_in[8];
    float* out = (float*)d_out;
    (void)in_sizes; (void)n_in; (void)out_size;

    static int smem_set = 0;
    if (!smem_set) {
        cudaFuncSetAttribute(lstm_seg, cudaFuncAttributeMaxDynamicSharedMemorySize, STEP_SMEM);
        smem_set = 1;
    }

    prep_misc<<<(B_SZ * HID + 255) / 256, 256>>>();
    prep_w<<<(GATES * WK + 255) / 256, 256>>>(W_cell);
    prep_e<<<dim3(GATES / 128, 1024 / 128), 256>>>(embed, W_cell, b_cell);

    gemm64<0><<<dim3(1024 / 64, B_SZ / 64), 256>>>(images, W_img, b_img, out, 1024, 2048);

    for (int t0 = 0; t0 < T_SZ; t0 += SEG) {
        const unsigned bar_base = 32u * (unsigned)(SEG - 1) * (unsigned)(t0 / SEG);
        lstm_seg<<<dim3(32, 4), NTHR, STEP_SMEM>>>(message, t0, bar_base);
    }

    gemm64<2><<<dim3(1024 / 64, B_SZ / 64), 256>>>(nullptr, W_hid, b_hid,
                                                   out + (size_t)B_SZ * HID, 1024, 1024);
}

// round 11
// speedup vs baseline: 3.3259x; 1.1043x over previous
#include <cuda_runtime.h>
#include <cuda_bf16.h>
#include <math.h>
#include <stdint.h>

#define B_SZ   512
#define T_SZ   128
#define HID    1024
#define EMB    512
#define GATES  4096
#define WK     1024      // recurrent K (h only)
#define NCH    16        // chunks of 64 K-elems
#define SEG    16        // steps per segment launch
#define NTHR   1024

// ---------------- device scratch (allocation-free) ----------------
__device__ __nv_bfloat16 g_Whi[GATES * WK];      // [p][k'] permuted N-major (h part)
__device__ __nv_bfloat16 g_Wlo[GATES * WK];
__device__ float g_Ep[1024 * GATES];             // E'[vocab][p]: emb@Wx + b (+1 on f)
__device__ __nv_bfloat16 g_hbhi[2][B_SZ * HID];  // double-buffered h (bf16 hi/lo)
__device__ __nv_bfloat16 g_hblo[2][B_SZ * HID];
__device__ float g_hf[B_SZ * HID];               // fp32 h (final projection)
__device__ float g_c[B_SZ * HID];
__device__ unsigned g_bar[128];                  // 4 m-group barriers, stride 32

// ---------------- helpers ----------------
__device__ __forceinline__ uint32_t smem_u32(const void* p) {
    uint32_t r;
    asm("{ .reg .u64 t; cvta.to.shared.u64 t, %1; cvt.u32.u64 %0, t; }" : "=r"(r) : "l"(p));
    return r;
}
__device__ __forceinline__ void cpa16(uint32_t dst, const void* src) {
    asm volatile("cp.async.cg.shared.global [%0], [%1], 16;" :: "r"(dst), "l"(src) : "memory");
}
#define CP_COMMIT() asm volatile("cp.async.commit_group;" ::: "memory")
#define CP_WAIT1()  asm volatile("cp.async.wait_group 1;" ::: "memory")
#define CP_WAIT0()  asm volatile("cp.async.wait_group 0;" ::: "memory")

#define LDMX4(r, addr) \
    asm volatile("ldmatrix.sync.aligned.m8n8.x4.shared.b16 {%0,%1,%2,%3}, [%4];" \
        : "=r"((r)[0]), "=r"((r)[1]), "=r"((r)[2]), "=r"((r)[3]) : "r"(addr))

#define MMA(acc, a, b0, b1) \
    asm volatile("mma.sync.aligned.m16n8k16.row.col.f32.bf16.bf16.f32 " \
        "{%0,%1,%2,%3}, {%4,%5,%6,%7}, {%8,%9}, {%0,%1,%2,%3};" \
        : "+f"((acc)[0]), "+f"((acc)[1]), "+f"((acc)[2]), "+f"((acc)[3]) \
        : "r"((a)[0]), "r"((a)[1]), "r"((a)[2]), "r"((a)[3]), "r"(b0), "r"(b1))

#define SW(o) ((uint32_t)(o) ^ ((((uint32_t)(o)) >> 3) & 0x70))

__device__ __forceinline__ float sigm(float x) { return 1.0f / (1.0f + __expf(-x)); }
__device__ __forceinline__ float tanh_f(float x) {
    float e = __expf(2.0f * x);
    return 1.0f - 2.0f / (e + 1.0f);
}

// smem: 3 stages; each stage = 4 regions (Ahi/Alo/Bhi/Blo) of 128 rows x 128B.
// smC overlaps slot 1 — disjoint from slot0/slot2 B regions (pre-barrier prefetch).
#define OFF_AHI   0
#define OFF_ALO   16384
#define OFF_BHI   32768
#define OFF_BLO   49152
#define STAGE_SZ  65536
#define STEP_SMEM (3 * STAGE_SZ)   // 196608

// one row per thread, one 16B quarter: 1024 threads cover 128 rows x 128B per region
#define PREF_A(base, kb) do { \
    cpa16((base) + OFF_AHI + sw0, aHhi + (kb) + go0); \
    cpa16((base) + OFF_ALO + sw0, aHlo + (kb) + go0); \
} while (0)
#define PREF_B(base, kb) do { \
    cpa16((base) + OFF_BHI + sw0, bWhi + (kb) + go0); \
    cpa16((base) + OFF_BLO + sw0, bWlo + (kb) + go0); \
} while (0)

// ================= LSTM segment: SEG steps, 1024 threads, bf16 3-pass =================
__global__ void __launch_bounds__(NTHR, 1)
lstm_seg(const int* __restrict__ message, int t0, unsigned bar_base)
{
    extern __shared__ __align__(1024) char smem[];
    const uint32_t sm = smem_u32(smem);
    const int tid  = threadIdx.x;
    const int lane = tid & 31;
    const int wid  = tid >> 5;              // 0..31
    const int bx   = blockIdx.x;            // n-tile 0..31 (permuted cols)
    const int bm   = blockIdx.y * 128;      // m-tile base row

    // ---- loader addressing: 1024 threads, 1 row + 1 quarter each ----
    const int r = tid >> 3;                 // 0..127 tile row
    const int q = tid & 7;                  // 16B quarter of 128B row
    const char* bWhi = (const char*)(g_Whi + (size_t)(bx * 128 + r) * WK);
    const char* bWlo = (const char*)(g_Wlo + (size_t)(bx * 128 + r) * WK);
    const char* hHi[2] = { (const char*)(g_hbhi[0] + (size_t)(bm + r) * HID),
                           (const char*)(g_hbhi[1] + (size_t)(bm + r) * HID) };
    const char* hLo[2] = { (const char*)(g_hblo[0] + (size_t)(bm + r) * HID),
                           (const char*)(g_hblo[1] + (size_t)(bm + r) * HID) };
    const uint32_t sw0 = SW(r * 128 + q * 16);
    const int go0 = q * 16;

    // ---- warp compute layout: 4(M) x 8(N) warps; warp tile 32x16 ----
    const int wm = (wid >> 3) * 32;
    const int wn = (wid & 7) * 16;
    const int aRow = (lane & 15);
    const int aSel = ((lane >> 4) & 1) * 16;
    const int bRowBase = (lane & 7) + ((lane >> 4) & 1) * 8;
    const int bSel = ((lane >> 3) & 1) * 16;

    // ---- epilogue addressing: 8 threads per row, 4 cols each ----
    const int erow  = bm + (tid >> 3);
    const int esub  = tid & 7;
    const int* msgp = message + erow * T_SZ;
    float* crow = g_c + (size_t)erow * HID + bx * 32 + esub * 4;
    float* hrow = g_hf + (size_t)erow * HID + bx * 32 + esub * 4;
    float* smC = (float*)(smem + STAGE_SZ);   // overlaps slot 1 (safe by schedule)

    // ---- initial pre-barrier weight prefetch (chunks 0 and 2; W only) ----
    PREF_B(sm, 0);
    PREF_B(sm + 2 * STAGE_SZ, 2 * 128);

    #pragma unroll 1
    for (int ts = 0; ts < SEG; ts++) {
        const int t = t0 + ts;
        const char* aHhi = hHi[t & 1];
        const char* aHlo = hLo[t & 1];

        float acc[2][2][4];
        #pragma unroll
        for (int i = 0; i < 2; i++)
            #pragma unroll
            for (int j = 0; j < 2; j++)
                #pragma unroll
                for (int k = 0; k < 4; k++) acc[i][j][k] = 0.0f;

        // ---- post-barrier: A chunk 0 (group also carries B0,B2), then chunk 1 A+B ----
        PREF_A(sm, 0);
        CP_COMMIT();
        PREF_A(sm + STAGE_SZ, 128);
        PREF_B(sm + STAGE_SZ, 128);
        CP_COMMIT();

        int sc = 0, sp = 2;
        #pragma unroll 1
        for (int c = 0; c < NCH; c++) {
            if (c < NCH - 1) { CP_WAIT1(); } else { CP_WAIT0(); }
            __syncthreads();   // chunk c visible to all; all warps done with slot sp

            if (c + 2 < NCH) {
                const uint32_t dst = sm + sp * STAGE_SZ;
                const int kb = (c + 2) * 128;
                PREF_A(dst, kb);
                if (c != 0) PREF_B(dst, kb);   // c==0: chunk2's B preloaded pre-barrier
                CP_COMMIT();
            }

            const uint32_t stage = sm + sc * STAGE_SZ;
            #pragma unroll
            for (int k16 = 0; k16 < 4; k16++) {
                const int kb = k16 * 32;
                uint32_t ah[2][4], al[2][4], bh[4], bl[4];
                #pragma unroll
                for (int mi = 0; mi < 2; mi++) {
                    const uint32_t ao = SW((wm + mi * 16 + aRow) * 128 + kb + aSel);
                    LDMX4(ah[mi], stage + OFF_AHI + ao);
                    LDMX4(al[mi], stage + OFF_ALO + ao);
                }
                {
                    const uint32_t bo = SW((wn + bRowBase) * 128 + kb + bSel);
                    LDMX4(bh, stage + OFF_BHI + bo);
                    LDMX4(bl, stage + OFF_BLO + bo);
                }
                #pragma unroll
                for (int mi = 0; mi < 2; mi++) {
                    #pragma unroll
                    for (int n8 = 0; n8 < 2; n8++) {
                        const uint32_t bh0 = bh[n8 * 2], bh1 = bh[n8 * 2 + 1];
                        const uint32_t bl0 = bl[n8 * 2], bl1 = bl[n8 * 2 + 1];
                        MMA(acc[mi][n8], ah[mi], bh0, bh1);
                        MMA(acc[mi][n8], al[mi], bh0, bh1);
                        MMA(acc[mi][n8], ah[mi], bl0, bl1);
                    }
                }
            }
            sc = (sc == 2) ? 0 : sc + 1;
            sp = (sp == 2) ? 0 : sp + 1;
        }

        __syncthreads();   // all warps done with all stage slots

        // ---- pre-barrier weight prefetch for NEXT step ----
        if (ts + 1 < SEG) {
            PREF_B(sm, 0);
            PREF_B(sm + 2 * STAGE_SZ, 2 * 128);
        }

        // ---- stage accumulators to smC (fp32, stride 132) ----
        #pragma unroll
        for (int mi = 0; mi < 2; mi++) {
            #pragma unroll
            for (int n8 = 0; n8 < 2; n8++) {
                const int row = wm + mi * 16 + (lane >> 2);
                const int col = wn + n8 * 8 + (lane & 3) * 2;
                smC[row * 132 + col]           = acc[mi][n8][0];
                smC[row * 132 + col + 1]       = acc[mi][n8][1];
                smC[(row + 8) * 132 + col]     = acc[mi][n8][2];
                smC[(row + 8) * 132 + col + 1] = acc[mi][n8][3];
            }
        }
        __syncthreads();

        // ---- fused epilogue: 8 threads per row, 4 elems each ----
        {
            const int msg = msgp[t];
            const float* cr = smC + (tid >> 3) * 132 + esub * 4;
            const float* ep = g_Ep + (size_t)msg * GATES + bx * 128 + esub * 4;
            __nv_bfloat16* hh = g_hbhi[(t + 1) & 1] + (size_t)erow * HID + bx * 32 + esub * 4;
            __nv_bfloat16* hl = g_hblo[(t + 1) & 1] + (size_t)erow * HID + bx * 32 + esub * 4;
            __nv_bfloat16 hhb[4], hlb[4];
            float hvb[4];
            #pragma unroll
            for (int l = 0; l < 4; l++) {
                const float iv = cr[l]      + ep[l];
                const float gv = cr[32 + l] + ep[32 + l];
                const float fv = cr[64 + l] + ep[64 + l];   // +1 folded
                const float ov = cr[96 + l] + ep[96 + l];
                const float cc = sigm(fv) * crow[l] + sigm(iv) * tanh_f(gv);
                const float hv = sigm(ov) * tanh_f(cc);
                crow[l] = cc;
                hvb[l] = hv;
                const __nv_bfloat16 hi = __float2bfloat16(hv);
                hhb[l] = hi;
                hlb[l] = __float2bfloat16(hv - __bfloat162float(hi));
            }
            *(int2*)hh = *(int2*)hhb;
            *(int2*)hl = *(int2*)hlb;
            if (t == T_SZ - 1) {
                *(float4*)hrow = *(float4*)hvb;
            }
        }

        // ---- per-m-group barrier (32 CTAs sharing this bm) ----
        if (ts + 1 < SEG) {
            __threadfence();
            __syncthreads();
            if (tid == 0) {
                unsigned* bar = g_bar + (blockIdx.y << 5);
                atomicAdd(bar, 1u);
                const unsigned target = bar_base + 32u * (unsigned)(ts + 1);
                while (*(volatile unsigned*)bar < target) { __nanosleep(64); }
            }
            __syncthreads();
        }
    }
}

// ================= prep kernels =================
__global__ void prep_w(const float* __restrict__ W)
{
    int idx = blockIdx.x * blockDim.x + threadIdx.x;
    if (idx >= GATES * WK) return;
    const int p  = idx / WK;
    const int k  = idx % WK;
    const int q = (p >> 5) & 3, j = p >> 7, l = p & 31;
    const int n = q * 1024 + j * 32 + l;
    const float w = W[(size_t)(EMB + k) * GATES + n];
    const __nv_bfloat16 hi = __float2bfloat16(w);
    g_Whi[idx] = hi;
    g_Wlo[idx] = __float2bfloat16(w - __bfloat162float(hi));
}

__global__ void prep_misc()
{
    int idx = blockIdx.x * blockDim.x + threadIdx.x;
    if (idx < 128) g_bar[idx] = 0u;
    if (idx < B_SZ * HID) {
        g_c[idx] = 0.0f;
        g_hbhi[0][idx] = __float2bfloat16(0.0f);
        g_hblo[0][idx] = __float2bfloat16(0.0f);
    }
}

// E'[v][p] = embed[v,:] @ W_cell[0:512, n(p)] + b[n] (+1 for f gate)
__global__ __launch_bounds__(256)
void prep_e(const float* __restrict__ A, const float* __restrict__ W,
            const float* __restrict__ bias)
{
    __shared__ float As[16][132];
    __shared__ float Bs[16][128];
    const int tid = threadIdx.x;
    const int bm = blockIdx.y * 128;
    const int bn = blockIdx.x * 128;
    const int K = EMB, N = GATES;

    const int ar0 = tid >> 2, ar1 = ar0 + 64, akq = (tid & 3) * 4;
    const int br0 = tid >> 5, br1 = br0 + 8, bc = (tid & 31) * 4;
    const int tm = (tid >> 4) * 8, tn = (tid & 15) * 8;

    float acc[8][8];
    #pragma unroll
    for (int i = 0; i < 8; i++)
        #pragma unroll
        for (int j = 0; j < 8; j++) acc[i][j] = 0.0f;

    for (int k0 = 0; k0 < K; k0 += 16) {
        const float4 va0 = *(const float4*)(A + (size_t)(bm + ar0) * K + k0 + akq);
        const float4 va1 = *(const float4*)(A + (size_t)(bm + ar1) * K + k0 + akq);
        const float4 vb0 = *(const float4*)(W + (size_t)(k0 + br0) * N + bn + bc);
        const float4 vb1 = *(const float4*)(W + (size_t)(k0 + br1) * N + bn + bc);
        As[akq + 0][ar0] = va0.x; As[akq + 1][ar0] = va0.y;
        As[akq + 2][ar0] = va0.z; As[akq + 3][ar0] = va0.w;
        As[akq + 0][ar1] = va1.x; As[akq + 1][ar1] = va1.y;
        As[akq + 2][ar1] = va1.z; As[akq + 3][ar1] = va1.w;
        *(float4*)&Bs[br0][bc] = vb0;
        *(float4*)&Bs[br1][bc] = vb1;
        __syncthreads();
        #pragma unroll
        for (int kk = 0; kk < 16; kk++) {
            float a[8], b[8];
            *(float4*)&a[0] = *(const float4*)&As[kk][tm];
            *(float4*)&a[4] = *(const float4*)&As[kk][tm + 4];
            *(float4*)&b[0] = *(const float4*)&Bs[kk][tn];
            *(float4*)&b[4] = *(const float4*)&Bs[kk][tn + 4];
            #pragma unroll
            for (int i = 0; i < 8; i++)
                #pragma unroll
                for (int j = 0; j < 8; j++)
                    acc[i][j] = fmaf(a[i], b[j], acc[i][j]);
        }
        __syncthreads();
    }

    const int q = bn >> 10;
    const float fadd = (q == 2) ? 1.0f : 0.0f;
    float bia[8];
    *(float4*)&bia[0] = *(const float4*)(bias + bn + tn);
    *(float4*)&bia[4] = *(const float4*)(bias + bn + tn + 4);
    const int n0 = bn + tn;
    const int j0 = (n0 >> 5) & 31, l0 = n0 & 31;
    const int p0 = j0 * 128 + q * 32 + l0;
    #pragma unroll
    for (int i = 0; i < 8; i++) {
        const int v = bm + tm + i;
        float4 o0, o1;
        o0.x = acc[i][0] + bia[0] + fadd; o0.y = acc[i][1] + bia[1] + fadd;
        o0.z = acc[i][2] + bia[2] + fadd; o0.w = acc[i][3] + bia[3] + fadd;
        o1.x = acc[i][4] + bia[4] + fadd; o1.y = acc[i][5] + bia[5] + fadd;
        o1.z = acc[i][6] + bia[6] + fadd; o1.w = acc[i][7] + bia[7] + fadd;
        float* dst = g_Ep + (size_t)v * GATES + p0;
        *(float4*)(dst)     = o0;
        *(float4*)(dst + 4) = o1;
    }
}

// ================= 64x64-tile SIMT fp32 GEMM (output projections) =================
template<int MODE>   // 0 = A param, 2 = A = g_hf
__global__ __launch_bounds__(256)
void gemm64(const float* __restrict__ A, const float* __restrict__ W,
            const float* __restrict__ bias, float* __restrict__ C,
            int N, int K)
{
    __shared__ float As[16][68];
    __shared__ float Bs[16][64];
    const int tid = threadIdx.x;
    const int bm = blockIdx.y * 64;
    const int bn = blockIdx.x * 64;
    const float* Ab = (MODE == 2) ? (const float*)g_hf : A;

    const int ar = tid >> 2, ak = (tid & 3) * 4;
    const int br = tid >> 4, bc = (tid & 15) * 4;
    const int tm = (tid >> 4) * 4, tn = (tid & 15) * 4;

    float acc[4][4];
    #pragma unroll
    for (int i = 0; i < 4; i++)
        #pragma unroll
        for (int j = 0; j < 4; j++) acc[i][j] = 0.0f;

    for (int k0 = 0; k0 < K; k0 += 16) {
        const float4 va = *(const float4*)(Ab + (size_t)(bm + ar) * K + k0 + ak);
        const float4 vb = *(const float4*)(W + (size_t)(k0 + br) * N + bn + bc);
        As[ak + 0][ar] = va.x; As[ak + 1][ar] = va.y;
        As[ak + 2][ar] = va.z; As[ak + 3][ar] = va.w;
        *(float4*)&Bs[br][bc] = vb;
        __syncthreads();
        #pragma unroll
        for (int kk = 0; kk < 16; kk++) {
            float a[4], b[4];
            *(float4*)&a[0] = *(const float4*)&As[kk][tm];
            *(float4*)&b[0] = *(const float4*)&Bs[kk][tn];
            #pragma unroll
            for (int i = 0; i < 4; i++)
                #pragma unroll
                for (int j = 0; j < 4; j++)
                    acc[i][j] = fmaf(a[i], b[j], acc[i][j]);
        }
        __syncthreads();
    }
    float4 bia = *(const float4*)(bias + bn + tn);
    #pragma unroll
    for (int i = 0; i < 4; i++) {
        float4 o;
        o.x = acc[i][0] + bia.x; o.y = acc[i][1] + bia.y;
        o.z = acc[i][2] + bia.z; o.w = acc[i][3] + bia.w;
        *(float4*)(C + (size_t)(bm + tm + i) * N + bn + tn) = o;
    }
}

// ================= launch =================
extern "C" void kernel_launch(void* const* d_in, const int* in_sizes, int n_in,
                              void* d_out, int out_size)
{
    const float* images  = (const float*)d_in[0];
    const float* embed   = (const float*)d_in[1];
    const float* W_cell  = (const float*)d_in[2];
    const float* b_cell  = (const float*)d_in[3];
    const float* W_img   = (const float*)d_in[4];
    const float* b_img   = (const float*)d_in[5];
    const float* W_hid   = (const float*)d_in[6];
    const float* b_hid   = (const float*)d_in[7];
    const int*   message = (const int*)d_in[8];
    float* out = (float*)d_out;
    (void)in_sizes; (void)n_in; (void)out_size;

    static int smem_set = 0;
    if (!smem_set) {
        cudaFuncSetAttribute(lstm_seg, cudaFuncAttributeMaxDynamicSharedMemorySize, STEP_SMEM);
        smem_set = 1;
    }

    prep_misc<<<(B_SZ * HID + 255) / 256, 256>>>();
    prep_w<<<(GATES * WK + 255) / 256, 256>>>(W_cell);
    prep_e<<<dim3(GATES / 128, 1024 / 128), 256>>>(embed, W_cell, b_cell);

    gemm64<0><<<dim3(1024 / 64, B_SZ / 64), 256>>>(images, W_img, b_img, out, 1024, 2048);

    for (int t0 = 0; t0 < T_SZ; t0 += SEG) {
        const unsigned bar_base = 32u * (unsigned)(SEG - 1) * (unsigned)(t0 / SEG);
        lstm_seg<<<dim3(32, 4), NTHR, STEP_SMEM>>>(message, t0, bar_base);
    }

    gemm64<2><<<dim3(1024 / 64, B_SZ / 64), 256>>>(nullptr, W_hid, b_hid,
                                                   out + (size_t)B_SZ * HID, 1024, 1024);
}

// round 12
// speedup vs baseline: 3.4499x; 1.0373x over previous
#include <cuda_runtime.h>
#include <cuda_bf16.h>
#include <math.h>
#include <stdint.h>

#define B_SZ   512
#define T_SZ   128
#define HID    1024
#define EMB    512
#define GATES  4096
#define WK     1024      // recurrent K (h only)
#define NCH    16        // chunks of 64 K-elems
#define SEG    16        // steps per segment launch
#define NTHR   1024

// ---------------- device scratch (allocation-free) ----------------
__device__ __nv_bfloat16 g_Whi[GATES * WK];      // [p][k'] permuted N-major (h part)
__device__ __nv_bfloat16 g_Wlo[GATES * WK];
__device__ float g_Ep[1024 * GATES];             // E'[vocab][p]: emb@Wx + b (+1 on f)
__device__ __nv_bfloat16 g_hbhi[2][B_SZ * HID];  // double-buffered h (bf16 hi/lo)
__device__ __nv_bfloat16 g_hblo[2][B_SZ * HID];
__device__ float g_hf[B_SZ * HID];               // fp32 h (final projection)
__device__ float g_c[B_SZ * HID];
__device__ unsigned g_bar[128];                  // 4 m-group barriers, stride 32

// ---------------- helpers ----------------
__device__ __forceinline__ uint32_t smem_u32(const void* p) {
    uint32_t r;
    asm("{ .reg .u64 t; cvta.to.shared.u64 t, %1; cvt.u32.u64 %0, t; }" : "=r"(r) : "l"(p));
    return r;
}
__device__ __forceinline__ void cpa16(uint32_t dst, const void* src) {
    asm volatile("cp.async.cg.shared.global [%0], [%1], 16;" :: "r"(dst), "l"(src) : "memory");
}
#define CP_COMMIT() asm volatile("cp.async.commit_group;" ::: "memory")
#define CP_WAIT1()  asm volatile("cp.async.wait_group 1;" ::: "memory")
#define CP_WAIT0()  asm volatile("cp.async.wait_group 0;" ::: "memory")

#define LDMX4(r, addr) \
    asm volatile("ldmatrix.sync.aligned.m8n8.x4.shared.b16 {%0,%1,%2,%3}, [%4];" \
        : "=r"((r)[0]), "=r"((r)[1]), "=r"((r)[2]), "=r"((r)[3]) : "r"(addr))

#define MMA(acc, a, b0, b1) \
    asm volatile("mma.sync.aligned.m16n8k16.row.col.f32.bf16.bf16.f32 " \
        "{%0,%1,%2,%3}, {%4,%5,%6,%7}, {%8,%9}, {%0,%1,%2,%3};" \
        : "+f"((acc)[0]), "+f"((acc)[1]), "+f"((acc)[2]), "+f"((acc)[3]) \
        : "r"((a)[0]), "r"((a)[1]), "r"((a)[2]), "r"((a)[3]), "r"(b0), "r"(b1))

#define SW(o) ((uint32_t)(o) ^ ((((uint32_t)(o)) >> 3) & 0x70))

__device__ __forceinline__ float sigm(float x) { return 1.0f / (1.0f + __expf(-x)); }
__device__ __forceinline__ float tanh_f(float x) {
    float e = __expf(2.0f * x);
    return 1.0f - 2.0f / (e + 1.0f);
}

// smem: 3 stages; each stage = 4 regions (Ahi/Alo/Bhi/Blo) of 128 rows x 128B.
// smC overlaps slot 1 — disjoint from slot0/slot2 B regions (pre-barrier prefetch).
#define OFF_AHI   0
#define OFF_ALO   16384
#define OFF_BHI   32768
#define OFF_BLO   49152
#define STAGE_SZ  65536
#define STEP_SMEM (3 * STAGE_SZ)   // 196608

// one row per thread, one 16B quarter: 1024 threads cover 128 rows x 128B per region
#define PREF_A(base, kb) do { \
    cpa16((base) + OFF_AHI + sw0, aHhi + (kb) + go0); \
    cpa16((base) + OFF_ALO + sw0, aHlo + (kb) + go0); \
} while (0)
#define PREF_B(base, kb) do { \
    cpa16((base) + OFF_BHI + sw0, bWhi + (kb) + go0); \
    cpa16((base) + OFF_BLO + sw0, bWlo + (kb) + go0); \
} while (0)

// ================= LSTM segment: SEG steps, 1024 threads, bf16 3-pass =================
__global__ void __launch_bounds__(NTHR, 1)
lstm_seg(const int* __restrict__ message, int t0, unsigned bar_base)
{
    extern __shared__ __align__(1024) char smem[];
    const uint32_t sm = smem_u32(smem);
    const int tid  = threadIdx.x;
    const int lane = tid & 31;
    const int wid  = tid >> 5;              // 0..31
    const int bx   = blockIdx.x;            // n-tile 0..31 (permuted cols)
    const int bm   = blockIdx.y * 128;      // m-tile base row

    // ---- loader addressing: 1024 threads, 1 row + 1 quarter each ----
    const int r = tid >> 3;                 // 0..127 tile row
    const int q = tid & 7;                  // 16B quarter of 128B row
    const char* bWhi = (const char*)(g_Whi + (size_t)(bx * 128 + r) * WK);
    const char* bWlo = (const char*)(g_Wlo + (size_t)(bx * 128 + r) * WK);
    const char* hHi[2] = { (const char*)(g_hbhi[0] + (size_t)(bm + r) * HID),
                           (const char*)(g_hbhi[1] + (size_t)(bm + r) * HID) };
    const char* hLo[2] = { (const char*)(g_hblo[0] + (size_t)(bm + r) * HID),
                           (const char*)(g_hblo[1] + (size_t)(bm + r) * HID) };
    const uint32_t sw0 = SW(r * 128 + q * 16);
    const int go0 = q * 16;

    // ---- warp compute layout: 4(M) x 8(N) warps; warp tile 32x16 ----
    const int wm = (wid >> 3) * 32;
    const int wn = (wid & 7) * 16;
    const int aRow = (lane & 15);
    const int aSel = ((lane >> 4) & 1) * 16;
    const int bRowBase = (lane & 7) + ((lane >> 4) & 1) * 8;
    const int bSel = ((lane >> 3) & 1) * 16;

    // ---- epilogue addressing: 8 threads per row, 4 cols each ----
    const int erow  = bm + (tid >> 3);
    const int esub  = tid & 7;
    const int* msgp = message + erow * T_SZ;
    float* crow = g_c + (size_t)erow * HID + bx * 32 + esub * 4;
    float* hrow = g_hf + (size_t)erow * HID + bx * 32 + esub * 4;
    float* smC = (float*)(smem + STAGE_SZ);   // overlaps slot 1 (safe by schedule)

    // cell state lives in registers for the whole segment (mapping is step-invariant)
    float4 creg = *(const float4*)crow;

    // ---- initial pre-barrier weight prefetch (chunks 0 and 2; W only) ----
    PREF_B(sm, 0);
    PREF_B(sm + 2 * STAGE_SZ, 2 * 128);

    #pragma unroll 1
    for (int ts = 0; ts < SEG; ts++) {
        const int t = t0 + ts;
        const int msg = msgp[t];            // independent of h; loads early
        const char* aHhi = hHi[t & 1];
        const char* aHlo = hLo[t & 1];

        float acc[2][2][4];
        #pragma unroll
        for (int i = 0; i < 2; i++)
            #pragma unroll
            for (int j = 0; j < 2; j++)
                #pragma unroll
                for (int k = 0; k < 4; k++) acc[i][j][k] = 0.0f;

        // ---- post-barrier: A chunk 0 (group also carries B0,B2), then chunk 1 A+B ----
        PREF_A(sm, 0);
        CP_COMMIT();
        PREF_A(sm + STAGE_SZ, 128);
        PREF_B(sm + STAGE_SZ, 128);
        CP_COMMIT();

        int sc = 0, sp = 2;
        #pragma unroll 1
        for (int c = 0; c < NCH; c++) {
            if (c < NCH - 1) { CP_WAIT1(); } else { CP_WAIT0(); }
            __syncthreads();   // chunk c visible to all; all warps done with slot sp

            if (c + 2 < NCH) {
                const uint32_t dst = sm + sp * STAGE_SZ;
                const int kb = (c + 2) * 128;
                PREF_A(dst, kb);
                if (c != 0) PREF_B(dst, kb);   // c==0: chunk2's B preloaded pre-barrier
                CP_COMMIT();
            }

            const uint32_t stage = sm + sc * STAGE_SZ;
            #pragma unroll
            for (int k16 = 0; k16 < 4; k16++) {
                const int kb = k16 * 32;
                uint32_t ah[2][4], al[2][4], bh[4], bl[4];
                #pragma unroll
                for (int mi = 0; mi < 2; mi++) {
                    const uint32_t ao = SW((wm + mi * 16 + aRow) * 128 + kb + aSel);
                    LDMX4(ah[mi], stage + OFF_AHI + ao);
                    LDMX4(al[mi], stage + OFF_ALO + ao);
                }
                {
                    const uint32_t bo = SW((wn + bRowBase) * 128 + kb + bSel);
                    LDMX4(bh, stage + OFF_BHI + bo);
                    LDMX4(bl, stage + OFF_BLO + bo);
                }
                #pragma unroll
                for (int mi = 0; mi < 2; mi++) {
                    #pragma unroll
                    for (int n8 = 0; n8 < 2; n8++) {
                        const uint32_t bh0 = bh[n8 * 2], bh1 = bh[n8 * 2 + 1];
                        const uint32_t bl0 = bl[n8 * 2], bl1 = bl[n8 * 2 + 1];
                        MMA(acc[mi][n8], ah[mi], bh0, bh1);
                        MMA(acc[mi][n8], al[mi], bh0, bh1);
                        MMA(acc[mi][n8], ah[mi], bl0, bl1);
                    }
                }
            }
            sc = (sc == 2) ? 0 : sc + 1;
            sp = (sp == 2) ? 0 : sp + 1;
        }

        __syncthreads();   // all warps done with all stage slots

        // ---- pre-barrier weight prefetch for NEXT step ----
        if (ts + 1 < SEG) {
            PREF_B(sm, 0);
            PREF_B(sm + 2 * STAGE_SZ, 2 * 128);
        }

        // ---- stage accumulators to smC (fp32, stride 132) ----
        #pragma unroll
        for (int mi = 0; mi < 2; mi++) {
            #pragma unroll
            for (int n8 = 0; n8 < 2; n8++) {
                const int row = wm + mi * 16 + (lane >> 2);
                const int col = wn + n8 * 8 + (lane & 3) * 2;
                smC[row * 132 + col]           = acc[mi][n8][0];
                smC[row * 132 + col + 1]       = acc[mi][n8][1];
                smC[(row + 8) * 132 + col]     = acc[mi][n8][2];
                smC[(row + 8) * 132 + col + 1] = acc[mi][n8][3];
            }
        }
        __syncthreads();

        // ---- fused epilogue: 8 threads per row, 4 elems each; c in registers ----
        {
            const float* cr = smC + (tid >> 3) * 132 + esub * 4;
            const float* ep = g_Ep + (size_t)msg * GATES + bx * 128 + esub * 4;
            __nv_bfloat16* hh = g_hbhi[(t + 1) & 1] + (size_t)erow * HID + bx * 32 + esub * 4;
            __nv_bfloat16* hl = g_hblo[(t + 1) & 1] + (size_t)erow * HID + bx * 32 + esub * 4;
            float* cv = (float*)&creg;
            __nv_bfloat16 hhb[4], hlb[4];
            float hvb[4];
            #pragma unroll
            for (int l = 0; l < 4; l++) {
                const float iv = cr[l]      + ep[l];
                const float gv = cr[32 + l] + ep[32 + l];
                const float fv = cr[64 + l] + ep[64 + l];   // +1 folded
                const float ov = cr[96 + l] + ep[96 + l];
                const float cc = sigm(fv) * cv[l] + sigm(iv) * tanh_f(gv);
                const float hv = sigm(ov) * tanh_f(cc);
                cv[l] = cc;
                hvb[l] = hv;
                const __nv_bfloat16 hi = __float2bfloat16(hv);
                hhb[l] = hi;
                hlb[l] = __float2bfloat16(hv - __bfloat162float(hi));
            }
            *(int2*)hh = *(int2*)hhb;
            *(int2*)hl = *(int2*)hlb;
            if (t == T_SZ - 1) {
                *(float4*)hrow = *(float4*)hvb;
            }
        }

        // ---- per-m-group barrier (32 CTAs sharing this bm) ----
        if (ts + 1 < SEG) {
            __threadfence();
            __syncthreads();
            if (tid == 0) {
                unsigned* bar = g_bar + (blockIdx.y << 5);
                atomicAdd(bar, 1u);
                const unsigned target = bar_base + 32u * (unsigned)(ts + 1);
                while (*(volatile unsigned*)bar < target) { __nanosleep(64); }
            }
            __syncthreads();
        }
    }

    // write back cell state for the next segment
    *(float4*)crow = creg;
}

// ================= prep kernels =================
__global__ void prep_w(const float* __restrict__ W)
{
    int idx = blockIdx.x * blockDim.x + threadIdx.x;
    if (idx >= GATES * WK) return;
    const int p  = idx / WK;
    const int k  = idx % WK;
    const int q = (p >> 5) & 3, j = p >> 7, l = p & 31;
    const int n = q * 1024 + j * 32 + l;
    const float w = W[(size_t)(EMB + k) * GATES + n];
    const __nv_bfloat16 hi = __float2bfloat16(w);
    g_Whi[idx] = hi;
    g_Wlo[idx] = __float2bfloat16(w - __bfloat162float(hi));
}

__global__ void prep_misc()
{
    int idx = blockIdx.x * blockDim.x + threadIdx.x;
    if (idx < 128) g_bar[idx] = 0u;
    if (idx < B_SZ * HID) {
        g_c[idx] = 0.0f;
        g_hbhi[0][idx] = __float2bfloat16(0.0f);
        g_hblo[0][idx] = __float2bfloat16(0.0f);
    }
}

// E'[v][p] = embed[v,:] @ W_cell[0:512, n(p)] + b[n] (+1 for f gate)
__global__ __launch_bounds__(256)
void prep_e(const float* __restrict__ A, const float* __restrict__ W,
            const float* __restrict__ bias)
{
    __shared__ float As[16][132];
    __shared__ float Bs[16][128];
    const int tid = threadIdx.x;
    const int bm = blockIdx.y * 128;
    const int bn = blockIdx.x * 128;
    const int K = EMB, N = GATES;

    const int ar0 = tid >> 2, ar1 = ar0 + 64, akq = (tid & 3) * 4;
    const int br0 = tid >> 5, br1 = br0 + 8, bc = (tid & 31) * 4;
    const int tm = (tid >> 4) * 8, tn = (tid & 15) * 8;

    float acc[8][8];
    #pragma unroll
    for (int i = 0; i < 8; i++)
        #pragma unroll
        for (int j = 0; j < 8; j++) acc[i][j] = 0.0f;

    for (int k0 = 0; k0 < K; k0 += 16) {
        const float4 va0 = *(const float4*)(A + (size_t)(bm + ar0) * K + k0 + akq);
        const float4 va1 = *(const float4*)(A + (size_t)(bm + ar1) * K + k0 + akq);
        const float4 vb0 = *(const float4*)(W + (size_t)(k0 + br0) * N + bn + bc);
        const float4 vb1 = *(const float4*)(W + (size_t)(k0 + br1) * N + bn + bc);
        As[akq + 0][ar0] = va0.x; As[akq + 1][ar0] = va0.y;
        As[akq + 2][ar0] = va0.z; As[akq + 3][ar0] = va0.w;
        As[akq + 0][ar1] = va1.x; As[akq + 1][ar1] = va1.y;
        As[akq + 2][ar1] = va1.z; As[akq + 3][ar1] = va1.w;
        *(float4*)&Bs[br0][bc] = vb0;
        *(float4*)&Bs[br1][bc] = vb1;
        __syncthreads();
        #pragma unroll
        for (int kk = 0; kk < 16; kk++) {
            float a[8], b[8];
            *(float4*)&a[0] = *(const float4*)&As[kk][tm];
            *(float4*)&a[4] = *(const float4*)&As[kk][tm + 4];
            *(float4*)&b[0] = *(const float4*)&Bs[kk][tn];
            *(float4*)&b[4] = *(const float4*)&Bs[kk][tn + 4];
            #pragma unroll
            for (int i = 0; i < 8; i++)
                #pragma unroll
                for (int j = 0; j < 8; j++)
                    acc[i][j] = fmaf(a[i], b[j], acc[i][j]);
        }
        __syncthreads();
    }

    const int q = bn >> 10;
    const float fadd = (q == 2) ? 1.0f : 0.0f;
    float bia[8];
    *(float4*)&bia[0] = *(const float4*)(bias + bn + tn);
    *(float4*)&bia[4] = *(const float4*)(bias + bn + tn + 4);
    const int n0 = bn + tn;
    const int j0 = (n0 >> 5) & 31, l0 = n0 & 31;
    const int p0 = j0 * 128 + q * 32 + l0;
    #pragma unroll
    for (int i = 0; i < 8; i++) {
        const int v = bm + tm + i;
        float4 o0, o1;
        o0.x = acc[i][0] + bia[0] + fadd; o0.y = acc[i][1] + bia[1] + fadd;
        o0.z = acc[i][2] + bia[2] + fadd; o0.w = acc[i][3] + bia[3] + fadd;
        o1.x = acc[i][4] + bia[4] + fadd; o1.y = acc[i][5] + bia[5] + fadd;
        o1.z = acc[i][6] + bia[6] + fadd; o1.w = acc[i][7] + bia[7] + fadd;
        float* dst = g_Ep + (size_t)v * GATES + p0;
        *(float4*)(dst)     = o0;
        *(float4*)(dst + 4) = o1;
    }
}

// ====== 64x64-tile fp32 GEMM, double-buffered + register prefetch (projections) ======
template<int MODE>   // 0 = A param, 2 = A = g_hf
__global__ __launch_bounds__(256)
void gemm64(const float* __restrict__ A, const float* __restrict__ W,
            const float* __restrict__ bias, float* __restrict__ C,
            int N, int K)
{
    __shared__ float As[2][16][68];
    __shared__ float Bs[2][16][64];
    const int tid = threadIdx.x;
    const int bm = blockIdx.y * 64;
    const int bn = blockIdx.x * 64;
    const float* Ab = (MODE == 2) ? (const float*)g_hf : A;

    const int ar = tid >> 2, ak = (tid & 3) * 4;
    const int br = tid >> 4, bc = (tid & 15) * 4;
    const int tm = (tid >> 4) * 4, tn = (tid & 15) * 4;

    const float* aP = Ab + (size_t)(bm + ar) * K + ak;
    const float* bP = W + (size_t)br * N + bn + bc;

    float acc[4][4];
    #pragma unroll
    for (int i = 0; i < 4; i++)
        #pragma unroll
        for (int j = 0; j < 4; j++) acc[i][j] = 0.0f;

    // preload block 0 into smem buf 0
    {
        const float4 va = *(const float4*)(aP);
        const float4 vb = *(const float4*)(bP);
        As[0][ak + 0][ar] = va.x; As[0][ak + 1][ar] = va.y;
        As[0][ak + 2][ar] = va.z; As[0][ak + 3][ar] = va.w;
        *(float4*)&Bs[0][br][bc] = vb;
    }
    __syncthreads();

    int buf = 0;
    for (int k0 = 16; k0 <= K; k0 += 16) {
        // issue next block's global loads (hidden behind compute)
        float4 nva, nvb;
        const bool more = (k0 < K);
        if (more) {
            nva = *(const float4*)(aP + k0);
            nvb = *(const float4*)(bP + (size_t)k0 * N);
        }

        #pragma unroll
        for (int kk = 0; kk < 16; kk++) {
            float a[4], b[4];
            *(float4*)&a[0] = *(const float4*)&As[buf][kk][tm];
            *(float4*)&b[0] = *(const float4*)&Bs[buf][kk][tn];
            #pragma unroll
            for (int i = 0; i < 4; i++)
                #pragma unroll
                for (int j = 0; j < 4; j++)
                    acc[i][j] = fmaf(a[i], b[j], acc[i][j]);
        }

        if (more) {
            const int nb = buf ^ 1;
            As[nb][ak + 0][ar] = nva.x; As[nb][ak + 1][ar] = nva.y;
            As[nb][ak + 2][ar] = nva.z; As[nb][ak + 3][ar] = nva.w;
            *(float4*)&Bs[nb][br][bc] = nvb;
        }
        __syncthreads();
        buf ^= 1;
    }

    float4 bia = *(const float4*)(bias + bn + tn);
    #pragma unroll
    for (int i = 0; i < 4; i++) {
        float4 o;
        o.x = acc[i][0] + bia.x; o.y = acc[i][1] + bia.y;
        o.z = acc[i][2] + bia.z; o.w = acc[i][3] + bia.w;
        *(float4*)(C + (size_t)(bm + tm + i) * N + bn + tn) = o;
    }
}

// ================= launch =================
extern "C" void kernel_launch(void* const* d_in, const int* in_sizes, int n_in,
                              void* d_out, int out_size)
{
    const float* images  = (const float*)d_in[0];
    const float* embed   = (const float*)d_in[1];
    const float* W_cell  = (const float*)d_in[2];
    const float* b_cell  = (const float*)d_in[3];
    const float* W_img   = (const float*)d_in[4];
    const float* b_img   = (const float*)d_in[5];
    const float* W_hid   = (const float*)d_in[6];
    const float* b_hid   = (const float*)d_in[7];
    const int*   message = (const int*)d_in[8];
    float* out = (float*)d_out;
    (void)in_sizes; (void)n_in; (void)out_size;

    static int smem_set = 0;
    if (!smem_set) {
        cudaFuncSetAttribute(lstm_seg, cudaFuncAttributeMaxDynamicSharedMemorySize, STEP_SMEM);
        smem_set = 1;
    }

    prep_misc<<<(B_SZ * HID + 255) / 256, 256>>>();
    prep_w<<<(GATES * WK + 255) / 256, 256>>>(W_cell);
    prep_e<<<dim3(GATES / 128, 1024 / 128), 256>>>(embed, W_cell, b_cell);

    gemm64<0><<<dim3(1024 / 64, B_SZ / 64), 256>>>(images, W_img, b_img, out, 1024, 2048);

    for (int t0 = 0; t0 < T_SZ; t0 += SEG) {
        const unsigned bar_base = 32u * (unsigned)(SEG - 1) * (unsigned)(t0 / SEG);
        lstm_seg<<<dim3(32, 4), NTHR, STEP_SMEM>>>(message, t0, bar_base);
    }

    gemm64<2><<<dim3(1024 / 64, B_SZ / 64), 256>>>(nullptr, W_hid, b_hid,
                                                   out + (size_t)B_SZ * HID, 1024, 1024);
}

// round 13
// speedup vs baseline: 3.5221x; 1.0209x over previous
#include <cuda_runtime.h>
#include <cuda_bf16.h>
#include <math.h>
#include <stdint.h>

#define B_SZ   512
#define T_SZ   128
#define HID    1024
#define EMB    512
#define GATES  4096
#define WK     1024      // recurrent K (h only)
#define NCH    16        // chunks of 64 K-elems
#define NTHR   1024

// ---------------- device scratch (allocation-free) ----------------
__device__ __nv_bfloat16 g_Whi[GATES * WK];      // [p][k'] permuted N-major (h part)
__device__ __nv_bfloat16 g_Wlo[GATES * WK];
__device__ float g_Ep[1024 * GATES];             // E'[vocab][p]: emb@Wx + b (+1 on f)
__device__ __nv_bfloat16 g_hbhi[2][B_SZ * HID];  // double-buffered h (bf16 hi/lo)
__device__ __nv_bfloat16 g_hblo[2][B_SZ * HID];
__device__ float g_hf[B_SZ * HID];               // fp32 h (final projection)
__device__ unsigned g_bar[128];                  // 4 m-group barriers, stride 32

// ---------------- helpers ----------------
__device__ __forceinline__ uint32_t smem_u32(const void* p) {
    uint32_t r;
    asm("{ .reg .u64 t; cvta.to.shared.u64 t, %1; cvt.u32.u64 %0, t; }" : "=r"(r) : "l"(p));
    return r;
}
__device__ __forceinline__ void cpa16(uint32_t dst, const void* src) {
    asm volatile("cp.async.cg.shared.global [%0], [%1], 16;" :: "r"(dst), "l"(src) : "memory");
}
#define CP_COMMIT() asm volatile("cp.async.commit_group;" ::: "memory")
#define CP_WAIT1()  asm volatile("cp.async.wait_group 1;" ::: "memory")
#define CP_WAIT0()  asm volatile("cp.async.wait_group 0;" ::: "memory")

#define LDMX4(r, addr) \
    asm volatile("ldmatrix.sync.aligned.m8n8.x4.shared.b16 {%0,%1,%2,%3}, [%4];" \
        : "=r"((r)[0]), "=r"((r)[1]), "=r"((r)[2]), "=r"((r)[3]) : "r"(addr))

#define MMA(acc, a, b0, b1) \
    asm volatile("mma.sync.aligned.m16n8k16.row.col.f32.bf16.bf16.f32 " \
        "{%0,%1,%2,%3}, {%4,%5,%6,%7}, {%8,%9}, {%0,%1,%2,%3};" \
        : "+f"((acc)[0]), "+f"((acc)[1]), "+f"((acc)[2]), "+f"((acc)[3]) \
        : "r"((a)[0]), "r"((a)[1]), "r"((a)[2]), "r"((a)[3]), "r"(b0), "r"(b1))

#define SW(o) ((uint32_t)(o) ^ ((((uint32_t)(o)) >> 3) & 0x70))

__device__ __forceinline__ float sigm(float x) { return 1.0f / (1.0f + __expf(-x)); }
__device__ __forceinline__ float tanh_f(float x) {
    float e = __expf(2.0f * x);
    return 1.0f - 2.0f / (e + 1.0f);
}

// smem: 3 stages; each stage = 4 regions (Ahi/Alo/Bhi/Blo) of 128 rows x 128B.
// smC overlaps slot 1 — disjoint from slot0/slot2 B regions (pre-barrier prefetch).
#define OFF_AHI   0
#define OFF_ALO   16384
#define OFF_BHI   32768
#define OFF_BLO   49152
#define STAGE_SZ  65536
#define STEP_SMEM (3 * STAGE_SZ)   // 196608

#define PREF_A(base, kb) do { \
    cpa16((base) + OFF_AHI + sw0, aHhi + (kb) + go0); \
    cpa16((base) + OFF_ALO + sw0, aHlo + (kb) + go0); \
} while (0)
#define PREF_B(base, kb) do { \
    cpa16((base) + OFF_BHI + sw0, bWhi + (kb) + go0); \
    cpa16((base) + OFF_BLO + sw0, bWlo + (kb) + go0); \
} while (0)

// ---------------- in-kernel images projection (16 extra CTAs) ----------------
// C[pm:+128][pn:+256] = images[512,2048] @ W_img[2048,1024] + b ; double-buffered
__device__ void proj_images(char* smem, const float* __restrict__ A,
                            const float* __restrict__ W, const float* __restrict__ bias,
                            float* __restrict__ C, int pm, int pn, int tid)
{
    const int K = 2048, N = 1024;
    float (*As)[16][132] = (float(*)[16][132])smem;                 // 16896 B
    float (*Bs)[16][256] = (float(*)[16][256])(smem + 18432);       // 32768 B

    const int ar = tid >> 3, ak = (tid & 7) * 2;    // A: 128 x 16, float2 each
    const int br = tid >> 6, bc = (tid & 63) * 4;   // B: 16 x 256, float4 each
    const int tm = (tid >> 5) * 4, tn = (tid & 31) * 8;

    const float* aP = A + (size_t)(pm + ar) * K + ak;
    const float* bP = W + (size_t)br * N + pn + bc;

    float acc[4][8];
    #pragma unroll
    for (int i = 0; i < 4; i++)
        #pragma unroll
        for (int j = 0; j < 8; j++) acc[i][j] = 0.0f;

    {
        const float2 va = *(const float2*)aP;
        const float4 vb = *(const float4*)bP;
        As[0][ak][ar] = va.x; As[0][ak + 1][ar] = va.y;
        *(float4*)&Bs[0][br][bc] = vb;
    }
    __syncthreads();

    int buf = 0;
    for (int k0 = 16; k0 <= K; k0 += 16) {
        const bool more = (k0 < K);
        float2 nva; float4 nvb;
        if (more) {
            nva = *(const float2*)(aP + k0);
            nvb = *(const float4*)(bP + (size_t)k0 * N);
        }
        #pragma unroll
        for (int kk = 0; kk < 16; kk++) {
            float a[4], b[8];
            *(float4*)&a[0] = *(const float4*)&As[buf][kk][tm];
            *(float4*)&b[0] = *(const float4*)&Bs[buf][kk][tn];
            *(float4*)&b[4] = *(const float4*)&Bs[buf][kk][tn + 4];
            #pragma unroll
            for (int i = 0; i < 4; i++)
                #pragma unroll
                for (int j = 0; j < 8; j++)
                    acc[i][j] = fmaf(a[i], b[j], acc[i][j]);
        }
        if (more) {
            const int nb = buf ^ 1;
            As[nb][ak][ar] = nva.x; As[nb][ak + 1][ar] = nva.y;
            *(float4*)&Bs[nb][br][bc] = nvb;
        }
        __syncthreads();
        buf ^= 1;
    }

    float bia[8];
    *(float4*)&bia[0] = *(const float4*)(bias + pn + tn);
    *(float4*)&bia[4] = *(const float4*)(bias + pn + tn + 4);
    #pragma unroll
    for (int i = 0; i < 4; i++) {
        float4 o0, o1;
        o0.x = acc[i][0] + bia[0]; o0.y = acc[i][1] + bia[1];
        o0.z = acc[i][2] + bia[2]; o0.w = acc[i][3] + bia[3];
        o1.x = acc[i][4] + bia[4]; o1.y = acc[i][5] + bia[5];
        o1.z = acc[i][6] + bia[6]; o1.w = acc[i][7] + bia[7];
        float* crow_ = C + (size_t)(pm + tm + i) * N + pn + tn;
        *(float4*)(crow_)     = o0;
        *(float4*)(crow_ + 4) = o1;
    }
}

// ========== persistent LSTM (all 128 steps) + overlapped images projection ==========
__global__ void __launch_bounds__(NTHR, 1)
lstm_persist(const int* __restrict__ message,
             const float* __restrict__ images, const float* __restrict__ W_img,
             const float* __restrict__ b_img, float* __restrict__ out)
{
    extern __shared__ __align__(1024) char smem[];
    const int tid = threadIdx.x;

    // ---- extra CTAs (bx >= 32): images projection on otherwise-idle SMs ----
    if (blockIdx.x >= 32) {
        const int id = (blockIdx.x - 32) * 4 + blockIdx.y;   // 0..15
        proj_images(smem, images, W_img, b_img, out,
                    (id >> 2) * 128, (id & 3) * 256, tid);
        return;
    }

    const uint32_t sm = smem_u32(smem);
    const int lane = tid & 31;
    const int wid  = tid >> 5;              // 0..31
    const int bx   = blockIdx.x;            // n-tile 0..31 (permuted cols)
    const int bm   = blockIdx.y * 128;      // m-tile base row

    // ---- loader addressing: 1024 threads, 1 row + 1 quarter each ----
    const int r = tid >> 3;                 // 0..127 tile row
    const int q = tid & 7;                  // 16B quarter of 128B row
    const char* bWhi = (const char*)(g_Whi + (size_t)(bx * 128 + r) * WK);
    const char* bWlo = (const char*)(g_Wlo + (size_t)(bx * 128 + r) * WK);
    const char* hHi[2] = { (const char*)(g_hbhi[0] + (size_t)(bm + r) * HID),
                           (const char*)(g_hbhi[1] + (size_t)(bm + r) * HID) };
    const char* hLo[2] = { (const char*)(g_hblo[0] + (size_t)(bm + r) * HID),
                           (const char*)(g_hblo[1] + (size_t)(bm + r) * HID) };
    const uint32_t sw0 = SW(r * 128 + q * 16);
    const int go0 = q * 16;

    // ---- warp compute layout: 4(M) x 8(N) warps; warp tile 32x16 ----
    const int wm = (wid >> 3) * 32;
    const int wn = (wid & 7) * 16;
    const int aRow = (lane & 15);
    const int aSel = ((lane >> 4) & 1) * 16;
    const int bRowBase = (lane & 7) + ((lane >> 4) & 1) * 8;
    const int bSel = ((lane >> 3) & 1) * 16;

    // ---- epilogue addressing: 8 threads per row, 4 cols each ----
    const int erow  = bm + (tid >> 3);
    const int esub  = tid & 7;
    const int* msgp = message + erow * T_SZ;
    float* hrow = g_hf + (size_t)erow * HID + bx * 32 + esub * 4;
    float* smC = (float*)(smem + STAGE_SZ);   // overlaps slot 1 (safe by schedule)

    // cell state lives in registers for ALL 128 steps (c0 = 0)
    float4 creg = make_float4(0.0f, 0.0f, 0.0f, 0.0f);

    // ---- initial pre-barrier weight prefetch (chunks 0 and 2; W only) ----
    PREF_B(sm, 0);
    PREF_B(sm + 2 * STAGE_SZ, 2 * 128);

    #pragma unroll 1
    for (int t = 0; t < T_SZ; t++) {
        const int msg = msgp[t];            // independent of h; loads early
        const char* aHhi = hHi[t & 1];
        const char* aHlo = hLo[t & 1];

        float acc[2][2][4];
        #pragma unroll
        for (int i = 0; i < 2; i++)
            #pragma unroll
            for (int j = 0; j < 2; j++)
                #pragma unroll
                for (int k = 0; k < 4; k++) acc[i][j][k] = 0.0f;

        // ---- post-barrier: A chunk 0 (group carries B0,B2), then chunk 1 A+B ----
        PREF_A(sm, 0);
        CP_COMMIT();
        PREF_A(sm + STAGE_SZ, 128);
        PREF_B(sm + STAGE_SZ, 128);
        CP_COMMIT();

        int sc = 0, sp = 2;
        #pragma unroll 1
        for (int c = 0; c < NCH; c++) {
            if (c < NCH - 1) { CP_WAIT1(); } else { CP_WAIT0(); }
            __syncthreads();   // chunk c visible to all; all warps done with slot sp

            if (c + 2 < NCH) {
                const uint32_t dst = sm + sp * STAGE_SZ;
                const int kb = (c + 2) * 128;
                PREF_A(dst, kb);
                if (c != 0) PREF_B(dst, kb);   // c==0: chunk2's B preloaded pre-barrier
                CP_COMMIT();
            }

            const uint32_t stage = sm + sc * STAGE_SZ;
            #pragma unroll
            for (int k16 = 0; k16 < 4; k16++) {
                const int kb = k16 * 32;
                uint32_t ah[2][4], al[2][4], bh[4], bl[4];
                #pragma unroll
                for (int mi = 0; mi < 2; mi++) {
                    const uint32_t ao = SW((wm + mi * 16 + aRow) * 128 + kb + aSel);
                    LDMX4(ah[mi], stage + OFF_AHI + ao);
                    LDMX4(al[mi], stage + OFF_ALO + ao);
                }
                {
                    const uint32_t bo = SW((wn + bRowBase) * 128 + kb + bSel);
                    LDMX4(bh, stage + OFF_BHI + bo);
                    LDMX4(bl, stage + OFF_BLO + bo);
                }
                #pragma unroll
                for (int mi = 0; mi < 2; mi++) {
                    #pragma unroll
                    for (int n8 = 0; n8 < 2; n8++) {
                        const uint32_t bh0 = bh[n8 * 2], bh1 = bh[n8 * 2 + 1];
                        const uint32_t bl0 = bl[n8 * 2], bl1 = bl[n8 * 2 + 1];
                        MMA(acc[mi][n8], ah[mi], bh0, bh1);
                        MMA(acc[mi][n8], al[mi], bh0, bh1);
                        MMA(acc[mi][n8], ah[mi], bl0, bl1);
                    }
                }
            }
            sc = (sc == 2) ? 0 : sc + 1;
            sp = (sp == 2) ? 0 : sp + 1;
        }

        __syncthreads();   // all warps done with all stage slots

        // ---- pre-barrier weight prefetch for NEXT step ----
        if (t + 1 < T_SZ) {
            PREF_B(sm, 0);
            PREF_B(sm + 2 * STAGE_SZ, 2 * 128);
        }

        // ---- stage accumulators to smC (fp32, stride 132) ----
        #pragma unroll
        for (int mi = 0; mi < 2; mi++) {
            #pragma unroll
            for (int n8 = 0; n8 < 2; n8++) {
                const int row = wm + mi * 16 + (lane >> 2);
                const int col = wn + n8 * 8 + (lane & 3) * 2;
                smC[row * 132 + col]           = acc[mi][n8][0];
                smC[row * 132 + col + 1]       = acc[mi][n8][1];
                smC[(row + 8) * 132 + col]     = acc[mi][n8][2];
                smC[(row + 8) * 132 + col + 1] = acc[mi][n8][3];
            }
        }
        __syncthreads();

        // ---- fused epilogue: 8 threads per row, 4 elems each; c in registers ----
        {
            const float* cr = smC + (tid >> 3) * 132 + esub * 4;
            const float* ep = g_Ep + (size_t)msg * GATES + bx * 128 + esub * 4;
            __nv_bfloat16* hh = g_hbhi[(t + 1) & 1] + (size_t)erow * HID + bx * 32 + esub * 4;
            __nv_bfloat16* hl = g_hblo[(t + 1) & 1] + (size_t)erow * HID + bx * 32 + esub * 4;
            float* cv = (float*)&creg;
            __nv_bfloat16 hhb[4], hlb[4];
            float hvb[4];
            #pragma unroll
            for (int l = 0; l < 4; l++) {
                const float iv = cr[l]      + ep[l];
                const float gv = cr[32 + l] + ep[32 + l];
                const float fv = cr[64 + l] + ep[64 + l];   // +1 folded
                const float ov = cr[96 + l] + ep[96 + l];
                const float cc = sigm(fv) * cv[l] + sigm(iv) * tanh_f(gv);
                const float hv = sigm(ov) * tanh_f(cc);
                cv[l] = cc;
                hvb[l] = hv;
                const __nv_bfloat16 hi = __float2bfloat16(hv);
                hhb[l] = hi;
                hlb[l] = __float2bfloat16(hv - __bfloat162float(hi));
            }
            *(int2*)hh = *(int2*)hhb;
            *(int2*)hl = *(int2*)hlb;
            if (t == T_SZ - 1) {
                *(float4*)hrow = *(float4*)hvb;
            }
        }

        // ---- per-m-group barrier (32 CTAs sharing this bm) ----
        if (t + 1 < T_SZ) {
            __threadfence();
            __syncthreads();
            if (tid == 0) {
                unsigned* bar = g_bar + (blockIdx.y << 5);
                atomicAdd(bar, 1u);
                const unsigned target = 32u * (unsigned)(t + 1);
                while (*(volatile unsigned*)bar < target) { __nanosleep(64); }
            }
            __syncthreads();
        }
    }
}

// ================= prep: W split/permute + h init + barrier reset =================
__global__ void prep_w(const float* __restrict__ W)
{
    int idx = blockIdx.x * blockDim.x + threadIdx.x;
    if (idx < 128) g_bar[idx] = 0u;
    if (idx < B_SZ * HID) {
        g_hbhi[0][idx] = __float2bfloat16(0.0f);
        g_hblo[0][idx] = __float2bfloat16(0.0f);
    }
    if (idx >= GATES * WK) return;
    const int p  = idx / WK;
    const int k  = idx % WK;
    const int q = (p >> 5) & 3, j = p >> 7, l = p & 31;
    const int n = q * 1024 + j * 32 + l;
    const float w = W[(size_t)(EMB + k) * GATES + n];
    const __nv_bfloat16 hi = __float2bfloat16(w);
    g_Whi[idx] = hi;
    g_Wlo[idx] = __float2bfloat16(w - __bfloat162float(hi));
}

// E'[v][p] = embed[v,:] @ W_cell[0:512, n(p)] + b[n] (+1 for f gate); double-buffered
__global__ __launch_bounds__(256)
void prep_e(const float* __restrict__ A, const float* __restrict__ W,
            const float* __restrict__ bias)
{
    __shared__ float As[2][16][132];
    __shared__ float Bs[2][16][128];
    const int tid = threadIdx.x;
    const int bm = blockIdx.y * 128;
    const int bn = blockIdx.x * 128;
    const int K = EMB, N = GATES;

    const int ar0 = tid >> 2, ar1 = ar0 + 64, akq = (tid & 3) * 4;
    const int br0 = tid >> 5, br1 = br0 + 8, bc = (tid & 31) * 4;
    const int tm = (tid >> 4) * 8, tn = (tid & 15) * 8;

    const float* aP0 = A + (size_t)(bm + ar0) * K + akq;
    const float* aP1 = A + (size_t)(bm + ar1) * K + akq;
    const float* bP0 = W + (size_t)br0 * N + bn + bc;
    const float* bP1 = W + (size_t)br1 * N + bn + bc;

    float acc[8][8];
    #pragma unroll
    for (int i = 0; i < 8; i++)
        #pragma unroll
        for (int j = 0; j < 8; j++) acc[i][j] = 0.0f;

    {
        const float4 va0 = *(const float4*)aP0;
        const float4 va1 = *(const float4*)aP1;
        const float4 vb0 = *(const float4*)bP0;
        const float4 vb1 = *(const float4*)bP1;
        As[0][akq + 0][ar0] = va0.x; As[0][akq + 1][ar0] = va0.y;
        As[0][akq + 2][ar0] = va0.z; As[0][akq + 3][ar0] = va0.w;
        As[0][akq + 0][ar1] = va1.x; As[0][akq + 1][ar1] = va1.y;
        As[0][akq + 2][ar1] = va1.z; As[0][akq + 3][ar1] = va1.w;
        *(float4*)&Bs[0][br0][bc] = vb0;
        *(float4*)&Bs[0][br1][bc] = vb1;
    }
    __syncthreads();

    int buf = 0;
    for (int k0 = 16; k0 <= K; k0 += 16) {
        const bool more = (k0 < K);
        float4 nva0, nva1, nvb0, nvb1;
        if (more) {
            nva0 = *(const float4*)(aP0 + k0);
            nva1 = *(const float4*)(aP1 + k0);
            nvb0 = *(const float4*)(bP0 + (size_t)k0 * N);
            nvb1 = *(const float4*)(bP1 + (size_t)k0 * N);
        }
        #pragma unroll
        for (int kk = 0; kk < 16; kk++) {
            float a[8], b[8];
            *(float4*)&a[0] = *(const float4*)&As[buf][kk][tm];
            *(float4*)&a[4] = *(const float4*)&As[buf][kk][tm + 4];
            *(float4*)&b[0] = *(const float4*)&Bs[buf][kk][tn];
            *(float4*)&b[4] = *(const float4*)&Bs[buf][kk][tn + 4];
            #pragma unroll
            for (int i = 0; i < 8; i++)
                #pragma unroll
                for (int j = 0; j < 8; j++)
                    acc[i][j] = fmaf(a[i], b[j], acc[i][j]);
        }
        if (more) {
            const int nb = buf ^ 1;
            As[nb][akq + 0][ar0] = nva0.x; As[nb][akq + 1][ar0] = nva0.y;
            As[nb][akq + 2][ar0] = nva0.z; As[nb][akq + 3][ar0] = nva0.w;
            As[nb][akq + 0][ar1] = nva1.x; As[nb][akq + 1][ar1] = nva1.y;
            As[nb][akq + 2][ar1] = nva1.z; As[nb][akq + 3][ar1] = nva1.w;
            *(float4*)&Bs[nb][br0][bc] = nvb0;
            *(float4*)&Bs[nb][br1][bc] = nvb1;
        }
        __syncthreads();
        buf ^= 1;
    }

    const int qg = bn >> 10;
    const float fadd = (qg == 2) ? 1.0f : 0.0f;
    float bia[8];
    *(float4*)&bia[0] = *(const float4*)(bias + bn + tn);
    *(float4*)&bia[4] = *(const float4*)(bias + bn + tn + 4);
    const int n0 = bn + tn;
    const int j0 = (n0 >> 5) & 31, l0 = n0 & 31;
    const int p0 = j0 * 128 + qg * 32 + l0;
    #pragma unroll
    for (int i = 0; i < 8; i++) {
        const int v = bm + tm + i;
        float4 o0, o1;
        o0.x = acc[i][0] + bia[0] + fadd; o0.y = acc[i][1] + bia[1] + fadd;
        o0.z = acc[i][2] + bia[2] + fadd; o0.w = acc[i][3] + bia[3] + fadd;
        o1.x = acc[i][4] + bia[4] + fadd; o1.y = acc[i][5] + bia[5] + fadd;
        o1.z = acc[i][6] + bia[6] + fadd; o1.w = acc[i][7] + bia[7] + fadd;
        float* dst = g_Ep + (size_t)v * GATES + p0;
        *(float4*)(dst)     = o0;
        *(float4*)(dst + 4) = o1;
    }
}

// ====== 64x64-tile fp32 GEMM, double-buffered (hidden projection) ======
__global__ __launch_bounds__(256)
void gemm64h(const float* __restrict__ W, const float* __restrict__ bias,
             float* __restrict__ C, int N, int K)
{
    __shared__ float As[2][16][68];
    __shared__ float Bs[2][16][64];
    const int tid = threadIdx.x;
    const int bm = blockIdx.y * 64;
    const int bn = blockIdx.x * 64;
    const float* Ab = (const float*)g_hf;

    const int ar = tid >> 2, ak = (tid & 3) * 4;
    const int br = tid >> 4, bc = (tid & 15) * 4;
    const int tm = (tid >> 4) * 4, tn = (tid & 15) * 4;

    const float* aP = Ab + (size_t)(bm + ar) * K + ak;
    const float* bP = W + (size_t)br * N + bn + bc;

    float acc[4][4];
    #pragma unroll
    for (int i = 0; i < 4; i++)
        #pragma unroll
        for (int j = 0; j < 4; j++) acc[i][j] = 0.0f;

    {
        const float4 va = *(const float4*)(aP);
        const float4 vb = *(const float4*)(bP);
        As[0][ak + 0][ar] = va.x; As[0][ak + 1][ar] = va.y;
        As[0][ak + 2][ar] = va.z; As[0][ak + 3][ar] = va.w;
        *(float4*)&Bs[0][br][bc] = vb;
    }
    __syncthreads();

    int buf = 0;
    for (int k0 = 16; k0 <= K; k0 += 16) {
        float4 nva, nvb;
        const bool more = (k0 < K);
        if (more) {
            nva = *(const float4*)(aP + k0);
            nvb = *(const float4*)(bP + (size_t)k0 * N);
        }
        #pragma unroll
        for (int kk = 0; kk < 16; kk++) {
            float a[4], b[4];
            *(float4*)&a[0] = *(const float4*)&As[buf][kk][tm];
            *(float4*)&b[0] = *(const float4*)&Bs[buf][kk][tn];
            #pragma unroll
            for (int i = 0; i < 4; i++)
                #pragma unroll
                for (int j = 0; j < 4; j++)
                    acc[i][j] = fmaf(a[i], b[j], acc[i][j]);
        }
        if (more) {
            const int nb = buf ^ 1;
            As[nb][ak + 0][ar] = nva.x; As[nb][ak + 1][ar] = nva.y;
            As[nb][ak + 2][ar] = nva.z; As[nb][ak + 3][ar] = nva.w;
            *(float4*)&Bs[nb][br][bc] = nvb;
        }
        __syncthreads();
        buf ^= 1;
    }

    float4 bia = *(const float4*)(bias + bn + tn);
    #pragma unroll
    for (int i = 0; i < 4; i++) {
        float4 o;
        o.x = acc[i][0] + bia.x; o.y = acc[i][1] + bia.y;
        o.z = acc[i][2] + bia.z; o.w = acc[i][3] + bia.w;
        *(float4*)(C + (size_t)(bm + tm + i) * N + bn + tn) = o;
    }
}

// ================= launch =================
extern "C" void kernel_launch(void* const* d_in, const int* in_sizes, int n_in,
                              void* d_out, int out_size)
{
    const float* images  = (const float*)d_in[0];
    const float* embed   = (const float*)d_in[1];
    const float* W_cell  = (const float*)d_in[2];
    const float* b_cell  = (const float*)d_in[3];
    const float* W_img   = (const float*)d_in[4];
    const float* b_img   = (const float*)d_in[5];
    const float* W_hid   = (const float*)d_in[6];
    const float* b_hid   = (const float*)d_in[7];
    const int*   message = (const int*)d_in[8];
    float* out = (float*)d_out;
    (void)in_sizes; (void)n_in; (void)out_size;

    static int smem_set = 0;
    if (!smem_set) {
        cudaFuncSetAttribute(lstm_persist, cudaFuncAttributeMaxDynamicSharedMemorySize, STEP_SMEM);
        smem_set = 1;
    }

    prep_w<<<(GATES * WK + 255) / 256, 256>>>(W_cell);
    prep_e<<<dim3(GATES / 128, 1024 / 128), 256>>>(embed, W_cell, b_cell);

    // 128 LSTM CTAs + 16 images-projection CTAs, all co-resident (144 <= 148 SMs)
    lstm_persist<<<dim3(36, 4), NTHR, STEP_SMEM>>>(message, images, W_img, b_img, out);

    gemm64h<<<dim3(1024 / 64, B_SZ / 64), 256>>>(W_hid, b_hid,
                                                 out + (size_t)B_SZ * HID, 1024, 1024);
}